// round 15
// baseline (speedup 1.0000x reference)
#include <cuda_runtime.h>
#include <cuda_fp16.h>
#include <math.h>
#include <stdint.h>

#define BM 128
#define BN 128
#define BKd 8
#define TM 8
#define TN 8

static constexpr int cB    = 4096;
static constexpr int cT    = 32;
static constexpr int cA    = 3;
static constexpr int cFLAT = 96;
static constexpr int cHID  = 1024;
static constexpr int cD    = 128;
static constexpr int cN    = 16;
static constexpr int cK    = 4096;
static constexpr int cLAT  = 2048;
static constexpr int cROWS = cB * cN;               // 65536
static constexpr int RECON_ELEMS = cB * cT * cA;    // 393216
static constexpr int IDX_OFF     = RECON_ELEMS;
static constexpr int SCALAR_OFF  = IDX_OFF + cROWS;
static constexpr int FULL_OUT    = SCALAR_OFF + 3;

static constexpr float SSCALE   = 256.0f;
static constexpr float LOSCALE  = 2048.0f;
static constexpr float INV_LO   = 4.8828125e-4f;     // 2^-11
static constexpr float INV_FULL = 1.52587890625e-5f; // 2^-16
static constexpr float EPS_SCALED = 2e-7f * 65536.0f;

static constexpr int L2_PARTS = 4;
static constexpr int L2_TILES_PER_PART = (cK / 128) / L2_PARTS;  // 8
static constexpr int FIXCAP = 2048;   // max samples needing decoder fixup

// ---------------- scratch ----------------
__device__ float g_h1 [cB * cHID];
__device__ float g_h2 [cB * cHID];
__device__ float g_lat[cB * cLAT];
__device__ float g_cn [cK];
__device__ float g_rn [cROWS];
__device__ int   g_idx[cROWS];
__device__ int   g_idx2[cROWS];
__device__ float g_vq_sum;
__device__ float g_recon_sum;
__device__ int   g_flagcnt;
__device__ int   g_flagrows[cROWS];
__device__ int   g_flagcnt2;
__device__ int   g_flagrows2[cROWS];
__device__ float g_cnmax;
__device__ float g_l2v[cROWS * L2_PARTS];
__device__ float g_l2s[cROWS * L2_PARTS];
__device__ int   g_l2i[cROWS * L2_PARTS];
__device__ int   g_nfixrows;
__device__ int   g_fixrows[cROWS];
__device__ int   g_nfixsamp;
__device__ int   g_fixsamp[cB];
__device__ int   g_sampflag[cB];
__device__ float g_qfix [FIXCAP * cLAT];
__device__ float g_gfix [FIXCAP * cHID];
__device__ __half g_gfixH[FIXCAP * cHID], g_gfixL[FIXCAP * cHID];

__device__ __half g_latH[cROWS * cD], g_latL[cROWS * cD];
__device__ __half g_qH [cB * cLAT],   g_qL [cB * cLAT];
__device__ __half g_g1H[cB * cHID],   g_g1L[cB * cHID];
__device__ __half g_g2H[cB * cHID],   g_g2L[cB * cHID];
__device__ __half g_cbH[cK * cD],     g_cbL[cK * cD];
__device__ __half g_v1H[cHID * cLAT],  g_v1L[cHID * cLAT];
__device__ __half g_v2H[cHID * cHID],  g_v2L[cHID * cHID];
__device__ __half g_v3H[cFLAT * cHID], g_v3L[cFLAT * cHID];

// ---------------- low-level helpers ----------------
typedef unsigned long long u64;
__device__ __forceinline__ u64 pack2(float lo, float hi) {
    u64 r;
    asm("mov.b64 %0, {%1, %2};" : "=l"(r) : "r"(__float_as_uint(lo)), "r"(__float_as_uint(hi)));
    return r;
}
__device__ __forceinline__ void fma2(u64 &d, u64 a, u64 b) {
    asm("fma.rn.f32x2 %0, %1, %2, %0;" : "+l"(d) : "l"(a), "l"(b));
}
__device__ __forceinline__ void unpack2(u64 v, float &lo, float &hi) {
    unsigned int l, h;
    asm("mov.b64 {%0, %1}, %2;" : "=r"(l), "=r"(h) : "l"(v));
    lo = __uint_as_float(l); hi = __uint_as_float(h);
}

__device__ __forceinline__ float silu_f(float x) {
    float s;
    if (x >= 0.0f) s = 1.0f / (1.0f + expf(-x));
    else { float e = expf(x); s = e / (1.0f + e); }
    return x * s;
}

__device__ __forceinline__ void mma16816(float c[4], uint32_t a0, uint32_t a1,
                                         uint32_t a2, uint32_t a3,
                                         uint32_t b0, uint32_t b1) {
    asm volatile(
        "mma.sync.aligned.m16n8k16.row.col.f32.f16.f16.f32 "
        "{%0,%1,%2,%3},{%4,%5,%6,%7},{%8,%9},{%0,%1,%2,%3};"
        : "+f"(c[0]), "+f"(c[1]), "+f"(c[2]), "+f"(c[3])
        : "r"(a0), "r"(a1), "r"(a2), "r"(a3), "r"(b0), "r"(b1));
}

__device__ __forceinline__ void ldsm4(uint32_t r[4], uint32_t addr) {
    asm volatile("ldmatrix.sync.aligned.m8n8.x4.shared.b16 {%0,%1,%2,%3}, [%4];"
                 : "=r"(r[0]), "=r"(r[1]), "=r"(r[2]), "=r"(r[3]) : "r"(addr));
}

__device__ __forceinline__ void cp_async16(void* dst, const void* src) {
    uint32_t d = (uint32_t)__cvta_generic_to_shared(dst);
    asm volatile("cp.async.cg.shared.global [%0], [%1], 16;" :: "r"(d), "l"(src));
}
#define CP_COMMIT() asm volatile("cp.async.commit_group;" ::: "memory")
#define CP_WAIT2()  asm volatile("cp.async.wait_group 2;" ::: "memory")

__global__ void init_accum() {
    int gid = blockIdx.x * 256 + threadIdx.x;
    if (gid < cB) g_sampflag[gid] = 0;
    if (gid == 0) {
        g_vq_sum = 0.0f; g_recon_sum = 0.0f;
        g_flagcnt = 0; g_flagcnt2 = 0;
        g_nfixrows = 0; g_nfixsamp = 0;
    }
}

__global__ void cn_kernel(const float* __restrict__ cb) {
    int warp = (blockIdx.x * blockDim.x + threadIdx.x) >> 5;
    int lane = threadIdx.x & 31;
    if (warp >= cK) return;
    const float4 v = reinterpret_cast<const float4*>(cb)[warp * 32 + lane];
    double a = (double)v.x * v.x + (double)v.y * v.y + (double)v.z * v.z + (double)v.w * v.w;
#pragma unroll
    for (int off = 16; off > 0; off >>= 1) a += __shfl_down_sync(0xffffffffu, a, off);
    if (lane == 0) g_cn[warp] = (float)a;
}

__global__ void cnmax_kernel() {
    __shared__ float red[256];
    float m = 0.0f;
    for (int i = threadIdx.x; i < cK; i += 256) m = fmaxf(m, g_cn[i]);
    red[threadIdx.x] = m;
    __syncthreads();
    for (int s = 128; s > 0; s >>= 1) {
        if (threadIdx.x < s) red[threadIdx.x] = fmaxf(red[threadIdx.x], red[threadIdx.x + s]);
        __syncthreads();
    }
    if (threadIdx.x == 0) g_cnmax = sqrtf(red[0]);
}

__global__ void rn_kernel(int rowoff) {
    int warp = rowoff + ((blockIdx.x * blockDim.x + threadIdx.x) >> 5);
    int lane = threadIdx.x & 31;
    if (warp >= cROWS) return;
    const float4 v = reinterpret_cast<const float4*>(g_lat)[(size_t)warp * 32 + lane];
    double a = (double)v.x * v.x + (double)v.y * v.y + (double)v.z * v.z + (double)v.w * v.w;
#pragma unroll
    for (int off = 16; off > 0; off >>= 1) a += __shfl_down_sync(0xffffffffu, a, off);
    if (lane == 0) g_rn[warp] = (float)a;
}

__global__ void split_act(const float* __restrict__ src, __half* __restrict__ hi,
                          __half* __restrict__ lo, int n4) {
    int i = blockIdx.x * blockDim.x + threadIdx.x;
    if (i >= n4) return;
    float4 v = reinterpret_cast<const float4*>(src)[i];
    float x0 = v.x * SSCALE, x1 = v.y * SSCALE, x2 = v.z * SSCALE, x3 = v.w * SSCALE;
    __half h0 = __float2half_rn(x0), h1 = __float2half_rn(x1);
    __half h2 = __float2half_rn(x2), h3 = __float2half_rn(x3);
    __half2* hp = reinterpret_cast<__half2*>(hi);
    hp[i * 2 + 0] = __half2(h0, h1);
    hp[i * 2 + 1] = __half2(h2, h3);
    __half2* lp = reinterpret_cast<__half2*>(lo);
    lp[i * 2 + 0] = __half2(__float2half_rn((x0 - __half2float(h0)) * LOSCALE),
                            __float2half_rn((x1 - __half2float(h1)) * LOSCALE));
    lp[i * 2 + 1] = __half2(__float2half_rn((x2 - __half2float(h2)) * LOSCALE),
                            __float2half_rn((x3 - __half2float(h3)) * LOSCALE));
}

__global__ void wsplit(const float* __restrict__ W, __half* __restrict__ WtH,
                       __half* __restrict__ WtL, int Kd, int N) {
    __shared__ float tile[32][33];
    const int bx = blockIdx.x * 32, by = blockIdx.y * 32;
    const int tx = threadIdx.x, ty = threadIdx.y;
    for (int r = ty; r < 32; r += 8) {
        int n = bx + tx;
        tile[r][tx] = (n < N) ? W[(size_t)(by + r) * N + n] : 0.0f;
    }
    __syncthreads();
    for (int r = ty; r < 32; r += 8) {
        int n = bx + r, k = by + tx;
        if (n < N) {
            float x = tile[tx][r] * SSCALE;
            __half h = __float2half_rn(x);
            WtH[(size_t)n * Kd + k] = h;
            WtL[(size_t)n * Kd + k] = __float2half_rn((x - __half2float(h)) * LOSCALE);
        }
    }
}

// ---------------- fp32 SGEMM (f32x2) — encoder + fixup GEMM ----------------
template <int MODE, bool SPLITOUT>
__global__ void __launch_bounds__(256)
sgemm_k(const float* __restrict__ Ag, const float* __restrict__ Bg,
        const float* __restrict__ bias, float* __restrict__ Cg,
        int M, int N, int Kd, __half* __restrict__ hiP, __half* __restrict__ loP,
        int yoff, const int* actCnt) {
    __shared__ float As[2][BKd][BM];
    __shared__ float Bs[2][BKd][BN];
    const int tid = threadIdx.x;
    const int rbase = (blockIdx.y + yoff) * BM, cbase = blockIdx.x * BN;
    if (actCnt != nullptr && rbase >= *actCnt) return;
    const int rowA = tid >> 1, colA4 = (tid & 1) * 4;
    const int rowB = tid >> 5, colB4 = (tid & 31) * 4;
    const int tr = (tid >> 4) * TM, tc = (tid & 15) * TN;

    u64 acc[TM][TN / 2];
#pragma unroll
    for (int i = 0; i < TM; i++)
#pragma unroll
        for (int j = 0; j < TN / 2; j++) acc[i][j] = 0ull;

    const int nt = Kd / BKd;
    const bool bok = (cbase + colB4 < N);

    {
        float4 pa = *reinterpret_cast<const float4*>(&Ag[(size_t)(rbase + rowA) * Kd + colA4]);
        float4 pb = make_float4(0.f, 0.f, 0.f, 0.f);
        if (bok) pb = *reinterpret_cast<const float4*>(&Bg[(size_t)rowB * N + cbase + colB4]);
        As[0][colA4 + 0][rowA] = pa.x; As[0][colA4 + 1][rowA] = pa.y;
        As[0][colA4 + 2][rowA] = pa.z; As[0][colA4 + 3][rowA] = pa.w;
        *reinterpret_cast<float4*>(&Bs[0][rowB][colB4]) = pb;
    }

    for (int t = 0; t < nt; t++) {
        const int cur = t & 1;
        float4 pa, pb;
        const bool more = (t + 1 < nt);
        if (more) {
            pa = *reinterpret_cast<const float4*>(
                &Ag[(size_t)(rbase + rowA) * Kd + (t + 1) * BKd + colA4]);
            pb = make_float4(0.f, 0.f, 0.f, 0.f);
            if (bok)
                pb = *reinterpret_cast<const float4*>(
                    &Bg[(size_t)((t + 1) * BKd + rowB) * N + cbase + colB4]);
        }
        __syncthreads();
#pragma unroll
        for (int k = 0; k < BKd; k++) {
            float4 a0 = *reinterpret_cast<const float4*>(&As[cur][k][tr]);
            float4 a1 = *reinterpret_cast<const float4*>(&As[cur][k][tr + 4]);
            const u64* bp = reinterpret_cast<const u64*>(&Bs[cur][k][tc]);
            u64 b0 = bp[0], b1 = bp[1], b2 = bp[2], b3 = bp[3];
            float am[TM] = {a0.x, a0.y, a0.z, a0.w, a1.x, a1.y, a1.z, a1.w};
#pragma unroll
            for (int i = 0; i < TM; i++) {
                u64 ap = pack2(am[i], am[i]);
                fma2(acc[i][0], ap, b0); fma2(acc[i][1], ap, b1);
                fma2(acc[i][2], ap, b2); fma2(acc[i][3], ap, b3);
            }
        }
        if (more) {
            const int nxt = cur ^ 1;
            As[nxt][colA4 + 0][rowA] = pa.x; As[nxt][colA4 + 1][rowA] = pa.y;
            As[nxt][colA4 + 2][rowA] = pa.z; As[nxt][colA4 + 3][rowA] = pa.w;
            *reinterpret_cast<float4*>(&Bs[nxt][rowB][colB4]) = pb;
        }
    }

#pragma unroll
    for (int i = 0; i < TM; i++) {
        const int row = rbase + tr + i;
#pragma unroll
        for (int j = 0; j < TN / 2; j++) {
            const int c0 = cbase + tc + 2 * j;
            if (c0 < N) {
                float lo, hi; unpack2(acc[i][j], lo, hi);
                float v0 = lo + bias[c0], v1 = hi + bias[c0 + 1];
                if (MODE == 1) { v0 = silu_f(v0); v1 = silu_f(v1); }
                Cg[(size_t)row * N + c0]     = v0;
                Cg[(size_t)row * N + c0 + 1] = v1;
                if (SPLITOUT) {
                    float x0 = v0 * SSCALE, x1 = v1 * SSCALE;
                    __half h0 = __float2half_rn(x0), h1 = __float2half_rn(x1);
                    *reinterpret_cast<__half2*>(&hiP[(size_t)row * N + c0]) = __half2(h0, h1);
                    *reinterpret_cast<__half2*>(&loP[(size_t)row * N + c0]) =
                        __half2(__float2half_rn((x0 - __half2float(h0)) * LOSCALE),
                                __float2half_rn((x1 - __half2float(h1)) * LOSCALE));
                }
            }
        }
    }
}

// ---------------- split-fp16 HMMA GEMM — decoder ----------------
static constexpr int KP   = 40;
static constexpr int STG  = 128 * KP;
static constexpr int DEC_SMEM = 4 * 2 * STG * 2;  // 81920 bytes

template <int MODE, int PASSES>
__global__ void __launch_bounds__(256)
mma_gemm(const __half* __restrict__ Ah, const __half* __restrict__ Al,
         const __half* __restrict__ Bh, const __half* __restrict__ Bl,
         const float* __restrict__ bias, float* __restrict__ Cg,
         __half* __restrict__ hiP, __half* __restrict__ loP,
         int M, int N, int Kd, const float* __restrict__ ref) {
    extern __shared__ __align__(16) __half dsm[];
    __half* As = dsm;
    __half* Bs = dsm + 4 * STG;

    const int tid = threadIdx.x;
    const int lane = tid & 31, warp = tid >> 5;
    const int wm = warp >> 2, wn = warp & 3;
    const int gq = lane >> 2, tq = lane & 3;
    const int rbase = blockIdx.y * 128, cbase = blockIdx.x * 128;

    const int KC = Kd >> 5;
    const int NCH = PASSES * KC;
    const int RESC = (PASSES > 1) ? (PASSES - 1) * KC : -1;

    if (N < 128) {
        const uint4 z4 = make_uint4(0, 0, 0, 0);
        for (int i = tid; i < 4 * STG / 8; i += 256)
            *reinterpret_cast<uint4*>(Bs + i * 8) = z4;
    }

    float acc[4][4][4];
#pragma unroll
    for (int a = 0; a < 4; a++)
#pragma unroll
        for (int b = 0; b < 4; b++)
#pragma unroll
            for (int c = 0; c < 4; c++) acc[a][b][c] = 0.0f;

    auto loadAB = [&](int c, int st) {
        const int p = c / KC, kc = c % KC;
        const __half* Asrc = (PASSES == 3 && p == 1) ? Al : Ah;
        const __half* Bsrc = (PASSES > 1 && p == 0) ? Bl : Bh;
#pragma unroll
        for (int j = 0; j < 2; j++) {
            int i = tid + 256 * j;
            int row = i >> 2, seg = i & 3;
            cp_async16(As + st * STG + row * KP + seg * 8,
                       Asrc + (size_t)(rbase + row) * Kd + kc * 32 + seg * 8);
            int col = cbase + row;
            if (col < N)
                cp_async16(Bs + st * STG + row * KP + seg * 8,
                           Bsrc + (size_t)col * Kd + kc * 32 + seg * 8);
        }
    };

    const uint32_t aRow = (lane & 7) + ((lane >> 3) & 1) * 8;
    const uint32_t aK   = (lane >> 4) * 8;
    const uint32_t bRow = ((lane >> 4) & 1) * 8 + (lane & 7);
    const uint32_t bK   = ((lane >> 3) & 1) * 8;
    const uint32_t aBase0 = (uint32_t)__cvta_generic_to_shared(As) +
                            ((wm * 64 + aRow) * KP + aK) * 2;
    const uint32_t bBase0 = (uint32_t)__cvta_generic_to_shared(Bs) +
                            ((wn * 32 + bRow) * KP + bK) * 2;

    loadAB(0, 0); CP_COMMIT();
    loadAB(1, 1); CP_COMMIT();
    for (int c = 0; c < NCH; c++) {
        if (c + 2 < NCH) loadAB(c + 2, (c + 2) & 3);
        CP_COMMIT();
        CP_WAIT2();
        __syncthreads();
        if (PASSES > 1 && c == RESC) {
#pragma unroll
            for (int a = 0; a < 4; a++)
#pragma unroll
                for (int b = 0; b < 4; b++)
#pragma unroll
                    for (int q = 0; q < 4; q++) acc[a][b][q] *= INV_LO;
        }
        const uint32_t aSt = aBase0 + ((c & 3) * STG) * 2;
        const uint32_t bSt = bBase0 + ((c & 3) * STG) * 2;
#pragma unroll
        for (int ks = 0; ks < 2; ks++) {
            const int k0 = ks * 16;
            uint32_t af[4][4];
#pragma unroll
            for (int mt = 0; mt < 4; mt++)
                ldsm4(af[mt], aSt + (mt * 16 * KP + k0) * 2);
            uint32_t bf[2][4];
#pragma unroll
            for (int pr = 0; pr < 2; pr++)
                ldsm4(bf[pr], bSt + (pr * 16 * KP + k0) * 2);
#pragma unroll
            for (int nt = 0; nt < 4; nt++) {
                uint32_t b0 = bf[nt >> 1][(nt & 1) * 2 + 0];
                uint32_t b1 = bf[nt >> 1][(nt & 1) * 2 + 1];
#pragma unroll
                for (int mt = 0; mt < 4; mt++)
                    mma16816(acc[mt][nt], af[mt][0], af[mt][1], af[mt][2], af[mt][3], b0, b1);
            }
        }
    }

    float lsum = 0.0f;
#pragma unroll
    for (int mt = 0; mt < 4; mt++) {
#pragma unroll
        for (int nt = 0; nt < 4; nt++) {
            const int row0 = rbase + wm * 64 + mt * 16 + gq;
            const int col0 = cbase + wn * 32 + nt * 8 + tq * 2;
            if (col0 < N) {
                const float bz0 = bias[col0], bz1 = bias[col0 + 1];
#pragma unroll
                for (int h = 0; h < 2; h++) {
                    const int row = row0 + 8 * h;
                    float v0 = acc[mt][nt][2 * h + 0] * INV_FULL + bz0;
                    float v1 = acc[mt][nt][2 * h + 1] * INV_FULL + bz1;
                    if (MODE == 1) {
                        v0 = silu_f(v0); v1 = silu_f(v1);
                        float x0 = v0 * SSCALE, x1 = v1 * SSCALE;
                        __half h0 = __float2half_rn(x0), h1 = __float2half_rn(x1);
                        *reinterpret_cast<__half2*>(&hiP[(size_t)row * N + col0]) = __half2(h0, h1);
                        *reinterpret_cast<__half2*>(&loP[(size_t)row * N + col0]) =
                            __half2(__float2half_rn((x0 - __half2float(h0)) * LOSCALE),
                                    __float2half_rn((x1 - __half2float(h1)) * LOSCALE));
                    } else {
                        Cg[(size_t)row * N + col0]     = v0;
                        Cg[(size_t)row * N + col0 + 1] = v1;
                        float d0 = v0 - ref[(size_t)row * N + col0];
                        float d1 = v1 - ref[(size_t)row * N + col0 + 1];
                        lsum = fmaf(d0, d0, fmaf(d1, d1, lsum));
                    }
                }
            }
        }
    }
    if (MODE == 2) {
        __shared__ float red[256];
        red[tid] = lsum; __syncthreads();
        for (int s = 128; s > 0; s >>= 1) { if (tid < s) red[tid] += red[tid + s]; __syncthreads(); }
        if (tid == 0) atomicAdd(&g_recon_sum, red[0]);
    }
}

// ---------------- Level-1 HMMA argmin — hi-only + sound flag ----------------
static constexpr int KPA = 136;
static constexpr int KPB = 40;
static constexpr int B_STGH = 128 * KPB;
static constexpr int ARG_SMEM1 =
    (128 * KPA + 4 * B_STGH) * 2 + (cK + 512 * 3) * 4;   // 98304

__global__ void __launch_bounds__(256)
argmin_l1(int boff) {
    extern __shared__ __align__(16) __half dsm[];
    __half* a_h = dsm;
    __half* bs  = dsm + 128 * KPA;
    float*  cn_s = reinterpret_cast<float*>(dsm + 128 * KPA + 4 * B_STGH);
    float*  RV = cn_s + cK;
    float*  RS = RV + 512;
    int*    RI = reinterpret_cast<int*>(RS + 512);

    const int tid = threadIdx.x;
    const int lane = tid & 31, warp = tid >> 5;
    const int wm = warp >> 2, wn = warp & 3;
    const int gq = lane >> 2, tq = lane & 3;
    const int rbase = (blockIdx.x + boff) * 128;

#pragma unroll
    for (int j = 0; j < 8; j++) {
        int i = tid + 256 * j;
        int row = i >> 4, seg = i & 15;
        *reinterpret_cast<uint4*>(a_h + row * KPA + seg * 8) =
            *reinterpret_cast<const uint4*>(g_latH + (size_t)(rbase + row) * cD + seg * 8);
    }
    for (int i = tid; i < cK / 4; i += 256) {
        float4 v = reinterpret_cast<const float4*>(g_cn)[i];
        v.x *= 65536.0f; v.y *= 65536.0f; v.z *= 65536.0f; v.w *= 65536.0f;
        reinterpret_cast<float4*>(cn_s)[i] = v;
    }

    float rnr[4][2];
#pragma unroll
    for (int mt = 0; mt < 4; mt++)
#pragma unroll
        for (int h = 0; h < 2; h++)
            rnr[mt][h] = g_rn[rbase + wm * 64 + mt * 16 + gq + 8 * h] * 65536.0f;

    float bv[4][2], sv[4][2];
    int   bi[4][2];
#pragma unroll
    for (int mt = 0; mt < 4; mt++)
#pragma unroll
        for (int h = 0; h < 2; h++) { bv[mt][h] = INFINITY; sv[mt][h] = INFINITY; bi[mt][h] = 0; }

    float acc[4][4][4];
#pragma unroll
    for (int a = 0; a < 4; a++)
#pragma unroll
        for (int b = 0; b < 4; b++)
#pragma unroll
            for (int q = 0; q < 4; q++) acc[a][b][q] = 0.0f;

    auto loadB = [&](int c, int st) {
        const int ct = c >> 2, kc = c & 3;
#pragma unroll
        for (int j = 0; j < 2; j++) {
            int i = tid + 256 * j;
            int row = i >> 2, seg = i & 3;
            cp_async16(bs + st * B_STGH + row * KPB + seg * 8,
                       g_cbH + (size_t)(ct * 128 + row) * cD + kc * 32 + seg * 8);
        }
    };

    const uint32_t aRow = (lane & 7) + ((lane >> 3) & 1) * 8;
    const uint32_t aK   = (lane >> 4) * 8;
    const uint32_t bRow = ((lane >> 4) & 1) * 8 + (lane & 7);
    const uint32_t bK   = ((lane >> 3) & 1) * 8;
    const uint32_t aBaseH = (uint32_t)__cvta_generic_to_shared(a_h) +
                            ((wm * 64 + aRow) * KPA + aK) * 2;
    const uint32_t bBase0 = (uint32_t)__cvta_generic_to_shared(bs) +
                            ((wn * 32 + bRow) * KPB + bK) * 2;

    const int NCHT = 32 * 4;
    loadB(0, 0); CP_COMMIT();
    loadB(1, 1); CP_COMMIT();
    for (int c = 0; c < NCHT; c++) {
        if (c + 2 < NCHT) loadB(c + 2, (c + 2) & 3);
        CP_COMMIT();
        CP_WAIT2();
        __syncthreads();
        const int kcc = c & 3;
        const uint32_t bSt = bBase0 + ((c & 3) * B_STGH) * 2;
#pragma unroll
        for (int ks = 0; ks < 2; ks++) {
            const int k0 = kcc * 32 + ks * 16;
            uint32_t af[4][4];
#pragma unroll
            for (int mt = 0; mt < 4; mt++)
                ldsm4(af[mt], aBaseH + (mt * 16 * KPA + k0) * 2);
            uint32_t bf[2][4];
#pragma unroll
            for (int pr = 0; pr < 2; pr++)
                ldsm4(bf[pr], bSt + (pr * 16 * KPB + ks * 16) * 2);
#pragma unroll
            for (int nt = 0; nt < 4; nt++) {
                uint32_t b0 = bf[nt >> 1][(nt & 1) * 2 + 0];
                uint32_t b1 = bf[nt >> 1][(nt & 1) * 2 + 1];
#pragma unroll
                for (int mt = 0; mt < 4; mt++)
                    mma16816(acc[mt][nt], af[mt][0], af[mt][1], af[mt][2], af[mt][3], b0, b1);
            }
        }
        if (kcc == 3) {
            const int ct = c >> 2;
#pragma unroll
            for (int mt = 0; mt < 4; mt++) {
#pragma unroll
                for (int nt = 0; nt < 4; nt++) {
                    const int col0 = ct * 128 + wn * 32 + nt * 8 + tq * 2;
#pragma unroll
                    for (int h = 0; h < 2; h++) {
#pragma unroll
                        for (int cc = 0; cc < 2; cc++) {
                            const int kg = col0 + cc;
                            float s1 = __fadd_rn(rnr[mt][h], cn_s[kg]);
                            float d  = __fadd_rn(s1, -2.0f * acc[mt][nt][2 * h + cc]);
                            if (d < bv[mt][h] || (d == bv[mt][h] && kg < bi[mt][h])) {
                                sv[mt][h] = bv[mt][h]; bv[mt][h] = d; bi[mt][h] = kg;
                            } else if (d < sv[mt][h]) {
                                sv[mt][h] = d;
                            }
                        }
                    }
                    acc[mt][nt][0] = 0.0f; acc[mt][nt][1] = 0.0f;
                    acc[mt][nt][2] = 0.0f; acc[mt][nt][3] = 0.0f;
                }
            }
        }
    }

#pragma unroll
    for (int mt = 0; mt < 4; mt++) {
#pragma unroll
        for (int h = 0; h < 2; h++) {
            float b = bv[mt][h], s = sv[mt][h];
            int   i = bi[mt][h];
#pragma unroll
            for (int m = 1; m <= 2; m <<= 1) {
                float b2 = __shfl_xor_sync(0xffffffffu, b, m);
                float s2 = __shfl_xor_sync(0xffffffffu, s, m);
                int   i2 = __shfl_xor_sync(0xffffffffu, i, m);
                if (b2 < b || (b2 == b && i2 < i)) { s = fminf(b, s2); b = b2; i = i2; }
                else s = fminf(s, b2);
            }
            if (tq == 0) {
                const int rl = wm * 64 + mt * 16 + gq + 8 * h;
                RV[rl * 4 + wn] = b; RS[rl * 4 + wn] = s; RI[rl * 4 + wn] = i;
            }
        }
    }
    __syncthreads();
    if (tid < 128) {
        float b = RV[tid * 4], s = RS[tid * 4];
        int   i = RI[tid * 4];
#pragma unroll
        for (int w = 1; w < 4; w++) {
            float b2 = RV[tid * 4 + w], s2 = RS[tid * 4 + w];
            int   i2 = RI[tid * 4 + w];
            if (b2 < b || (b2 == b && i2 < i)) { s = fminf(b, s2); b = b2; i = i2; }
            else s = fminf(s, b2);
        }
        g_idx[rbase + tid] = i;
        float thr = 96.0f * sqrtf(g_rn[rbase + tid]) * g_cnmax + 0.01f;
        if (s - b < thr) {
            int p = atomicAdd(&g_flagcnt, 1);
            g_flagrows[p] = rbase + tid;
        }
    }
}

// ---------------- Level-2 HMMA argmin — 3-pass, code-partitioned (shadow idx) ----------------
static constexpr int ARG_SMEM2 =
    (256 * KPA + 4 * B_STGH) * 2 + (cK + 512 * 3) * 4 + 512;   // ~133.6KB

__global__ void __launch_bounds__(256)
argmin_l2() {
    extern __shared__ __align__(16) __half dsm[];
    __half* a_h = dsm;
    __half* a_l = dsm + 128 * KPA;
    __half* bs  = dsm + 256 * KPA;
    float*  cn_s = reinterpret_cast<float*>(dsm + 256 * KPA + 4 * B_STGH);
    float*  RV = cn_s + cK;
    float*  RS = RV + 512;
    int*    RI = reinterpret_cast<int*>(RS + 512);
    int*    rid_s = RI + 512;

    const int nf = g_flagcnt;
    const int ntiles = (nf + 127) >> 7;
    if ((int)blockIdx.x >= ntiles) return;

    const int tid = threadIdx.x;
    const int lane = tid & 31, warp = tid >> 5;
    const int wm = warp >> 2, wn = warp & 3;
    const int gq = lane >> 2, tq = lane & 3;
    const int base = blockIdx.x * 128;
    const int part = blockIdx.y;
    const int ct0 = part * L2_TILES_PER_PART;

    if (tid < 128) {
        int f = base + tid;
        rid_s[tid] = g_flagrows[(f < nf) ? f : (nf - 1)];
    }
    __syncthreads();

#pragma unroll
    for (int j = 0; j < 8; j++) {
        int i = tid + 256 * j;
        int row = i >> 4, seg = i & 15;
        int ridx = rid_s[row];
        *reinterpret_cast<uint4*>(a_h + row * KPA + seg * 8) =
            *reinterpret_cast<const uint4*>(g_latH + (size_t)ridx * cD + seg * 8);
        *reinterpret_cast<uint4*>(a_l + row * KPA + seg * 8) =
            *reinterpret_cast<const uint4*>(g_latL + (size_t)ridx * cD + seg * 8);
    }
    for (int i = tid; i < cK / 4; i += 256) {
        float4 v = reinterpret_cast<const float4*>(g_cn)[i];
        v.x *= 65536.0f; v.y *= 65536.0f; v.z *= 65536.0f; v.w *= 65536.0f;
        reinterpret_cast<float4*>(cn_s)[i] = v;
    }

    float rnr[4][2];
#pragma unroll
    for (int mt = 0; mt < 4; mt++)
#pragma unroll
        for (int h = 0; h < 2; h++)
            rnr[mt][h] = g_rn[rid_s[wm * 64 + mt * 16 + gq + 8 * h]] * 65536.0f;

    float bv[4][2], sv[4][2];
    int   bi[4][2];
#pragma unroll
    for (int mt = 0; mt < 4; mt++)
#pragma unroll
        for (int h = 0; h < 2; h++) { bv[mt][h] = INFINITY; sv[mt][h] = INFINITY; bi[mt][h] = 0; }

    float acc[4][4][4];
#pragma unroll
    for (int a = 0; a < 4; a++)
#pragma unroll
        for (int b = 0; b < 4; b++)
#pragma unroll
            for (int q = 0; q < 4; q++) acc[a][b][q] = 0.0f;

    auto loadB = [&](int c, int st) {
        const int ct = ct0 + c / 12, sub = c % 12;
        const __half* src = ((sub >> 2) == 0) ? g_cbL : g_cbH;
        const int kc = sub & 3;
#pragma unroll
        for (int j = 0; j < 2; j++) {
            int i = tid + 256 * j;
            int row = i >> 2, seg = i & 3;
            cp_async16(bs + st * B_STGH + row * KPB + seg * 8,
                       src + (size_t)(ct * 128 + row) * cD + kc * 32 + seg * 8);
        }
    };

    const uint32_t aRow = (lane & 7) + ((lane >> 3) & 1) * 8;
    const uint32_t aK   = (lane >> 4) * 8;
    const uint32_t bRow = ((lane >> 4) & 1) * 8 + (lane & 7);
    const uint32_t bK   = ((lane >> 3) & 1) * 8;
    const uint32_t aBaseH = (uint32_t)__cvta_generic_to_shared(a_h) +
                            ((wm * 64 + aRow) * KPA + aK) * 2;
    const uint32_t aBaseL = (uint32_t)__cvta_generic_to_shared(a_l) +
                            ((wm * 64 + aRow) * KPA + aK) * 2;
    const uint32_t bBase0 = (uint32_t)__cvta_generic_to_shared(bs) +
                            ((wn * 32 + bRow) * KPB + bK) * 2;

    const int NCHT = L2_TILES_PER_PART * 12;   // 96
    loadB(0, 0); CP_COMMIT();
    loadB(1, 1); CP_COMMIT();
    for (int c = 0; c < NCHT; c++) {
        if (c + 2 < NCHT) loadB(c + 2, (c + 2) & 3);
        CP_COMMIT();
        CP_WAIT2();
        __syncthreads();
        const int sub = c % 12;
        if (sub == 8) {
#pragma unroll
            for (int a = 0; a < 4; a++)
#pragma unroll
                for (int b = 0; b < 4; b++)
#pragma unroll
                    for (int q = 0; q < 4; q++) acc[a][b][q] *= INV_LO;
        }
        const int kcc = sub & 3;
        const uint32_t aBase = ((sub >> 2) == 1) ? aBaseL : aBaseH;
        const uint32_t bSt = bBase0 + ((c & 3) * B_STGH) * 2;
#pragma unroll
        for (int ks = 0; ks < 2; ks++) {
            const int k0 = kcc * 32 + ks * 16;
            uint32_t af[4][4];
#pragma unroll
            for (int mt = 0; mt < 4; mt++)
                ldsm4(af[mt], aBase + (mt * 16 * KPA + k0) * 2);
            uint32_t bf[2][4];
#pragma unroll
            for (int pr = 0; pr < 2; pr++)
                ldsm4(bf[pr], bSt + (pr * 16 * KPB + ks * 16) * 2);
#pragma unroll
            for (int nt = 0; nt < 4; nt++) {
                uint32_t b0 = bf[nt >> 1][(nt & 1) * 2 + 0];
                uint32_t b1 = bf[nt >> 1][(nt & 1) * 2 + 1];
#pragma unroll
                for (int mt = 0; mt < 4; mt++)
                    mma16816(acc[mt][nt], af[mt][0], af[mt][1], af[mt][2], af[mt][3], b0, b1);
            }
        }
        if (sub == 11) {
            const int ct = ct0 + c / 12;
#pragma unroll
            for (int mt = 0; mt < 4; mt++) {
#pragma unroll
                for (int nt = 0; nt < 4; nt++) {
                    const int col0 = ct * 128 + wn * 32 + nt * 8 + tq * 2;
#pragma unroll
                    for (int h = 0; h < 2; h++) {
#pragma unroll
                        for (int cc = 0; cc < 2; cc++) {
                            const int kg = col0 + cc;
                            float s1 = __fadd_rn(rnr[mt][h], cn_s[kg]);
                            float d  = __fadd_rn(s1, -2.0f * acc[mt][nt][2 * h + cc]);
                            if (d < bv[mt][h] || (d == bv[mt][h] && kg < bi[mt][h])) {
                                sv[mt][h] = bv[mt][h]; bv[mt][h] = d; bi[mt][h] = kg;
                            } else if (d < sv[mt][h]) {
                                sv[mt][h] = d;
                            }
                        }
                    }
                    acc[mt][nt][0] = 0.0f; acc[mt][nt][1] = 0.0f;
                    acc[mt][nt][2] = 0.0f; acc[mt][nt][3] = 0.0f;
                }
            }
        }
    }

#pragma unroll
    for (int mt = 0; mt < 4; mt++) {
#pragma unroll
        for (int h = 0; h < 2; h++) {
            float b = bv[mt][h], s = sv[mt][h];
            int   i = bi[mt][h];
#pragma unroll
            for (int m = 1; m <= 2; m <<= 1) {
                float b2 = __shfl_xor_sync(0xffffffffu, b, m);
                float s2 = __shfl_xor_sync(0xffffffffu, s, m);
                int   i2 = __shfl_xor_sync(0xffffffffu, i, m);
                if (b2 < b || (b2 == b && i2 < i)) { s = fminf(b, s2); b = b2; i = i2; }
                else s = fminf(s, b2);
            }
            if (tq == 0) {
                const int rl = wm * 64 + mt * 16 + gq + 8 * h;
                RV[rl * 4 + wn] = b; RS[rl * 4 + wn] = s; RI[rl * 4 + wn] = i;
            }
        }
    }
    __syncthreads();
    if (tid < 128 && base + tid < nf) {
        float b = RV[tid * 4], s = RS[tid * 4];
        int   i = RI[tid * 4];
#pragma unroll
        for (int w = 1; w < 4; w++) {
            float b2 = RV[tid * 4 + w], s2 = RS[tid * 4 + w];
            int   i2 = RI[tid * 4 + w];
            if (b2 < b || (b2 == b && i2 < i)) { s = fminf(b, s2); b = b2; i = i2; }
            else s = fminf(s, b2);
        }
        const int f = base + tid;
        g_l2v[f * L2_PARTS + part] = b;
        g_l2s[f * L2_PARTS + part] = s;
        g_l2i[f * L2_PARTS + part] = i;
    }
}

__global__ void l2_combine() {
    int f = blockIdx.x * 256 + threadIdx.x;
    const int nf = g_flagcnt;
    if (f >= nf) return;
    float b = g_l2v[f * L2_PARTS], s = g_l2s[f * L2_PARTS];
    int   i = g_l2i[f * L2_PARTS];
#pragma unroll
    for (int w = 1; w < L2_PARTS; w++) {
        float b2 = g_l2v[f * L2_PARTS + w], s2 = g_l2s[f * L2_PARTS + w];
        int   i2 = g_l2i[f * L2_PARTS + w];
        if (b2 < b || (b2 == b && i2 < i)) { s = fminf(b, s2); b = b2; i = i2; }
        else s = fminf(s, b2);
    }
    const int row = g_flagrows[f];
    g_idx2[row] = i;                      // shadow write (no race with speculative decode)
    if (s - b < EPS_SCALED) {
        int p = atomicAdd(&g_flagcnt2, 1);
        g_flagrows2[p] = row;
    }
}

// ---------------- Level-3 exact fp32 recheck (shadow idx) ----------------
__global__ void __launch_bounds__(256)
recheck_k(const float* __restrict__ cb) {
    __shared__ float lrow[32][cD + 4];
    __shared__ float crow[8][cD + 4];
    __shared__ int   rowid[32];
    __shared__ float rnv[32];
    const int tid = threadIdx.x;
    const int nf = g_flagcnt2;
    const int ntiles = (nf + 31) >> 5;
    const int r = tid >> 3;
    const int cl = tid & 7;

    for (int tile = blockIdx.x; tile < ntiles; tile += gridDim.x) {
        __syncthreads();
        if (tid < 32) {
            int f = tile * 32 + tid;
            int row = (f < nf) ? g_flagrows2[f] : -1;
            rowid[tid] = row;
            rnv[tid] = (row >= 0) ? g_rn[row] : 0.0f;
        }
        __syncthreads();
        for (int i = tid; i < 32 * 32; i += 256) {
            int rr = i >> 5, seg = i & 31;
            int row = rowid[rr];
            float4 v = (row >= 0)
                ? reinterpret_cast<const float4*>(g_lat + (size_t)row * cD)[seg]
                : make_float4(0.f, 0.f, 0.f, 0.f);
            *reinterpret_cast<float4*>(&lrow[rr][seg * 4]) = v;
        }
        __syncthreads();

        float bvv = INFINITY; int bii = 0;
        const float rn = rnv[r];
        for (int k0 = 0; k0 < cK; k0 += 8) {
            {
                int cr = tid >> 5, seg = tid & 31;
                *reinterpret_cast<float4*>(&crow[cr][seg * 4]) =
                    reinterpret_cast<const float4*>(cb + (size_t)(k0 + cr) * cD)[seg];
            }
            __syncthreads();
            float dot = 0.0f;
#pragma unroll
            for (int d4 = 0; d4 < 32; d4++) {
                float4 a = *reinterpret_cast<const float4*>(&lrow[r][d4 * 4]);
                float4 b = *reinterpret_cast<const float4*>(&crow[cl][d4 * 4]);
                dot = fmaf(a.x, b.x, dot); dot = fmaf(a.y, b.y, dot);
                dot = fmaf(a.z, b.z, dot); dot = fmaf(a.w, b.w, dot);
            }
            const int k = k0 + cl;
            float s1 = __fadd_rn(rn, g_cn[k]);
            float dd = __fadd_rn(s1, -2.0f * dot);
            if (dd < bvv) { bvv = dd; bii = k; }
            __syncthreads();
        }
#pragma unroll
        for (int m = 1; m <= 4; m <<= 1) {
            float b2 = __shfl_xor_sync(0xffffffffu, bvv, m);
            int   i2 = __shfl_xor_sync(0xffffffffu, bii, m);
            if (b2 < bvv || (b2 == bvv && i2 < bii)) { bvv = b2; bii = i2; }
        }
        if (cl == 0 && rowid[r] >= 0) g_idx2[rowid[r]] = bii;
    }
}

// detect rows whose final index differs from the speculative (L1) index
__global__ void fixdetect() {
    int f = blockIdx.x * 256 + threadIdx.x;
    if (f >= g_flagcnt) return;
    int row = g_flagrows[f];
    int ni = g_idx2[row];
    if (ni != g_idx[row]) {
        int p = atomicAdd(&g_nfixrows, 1);
        g_fixrows[p] = row;
        int b = row >> 4;
        if (atomicExch(&g_sampflag[b], 1) == 0) {
            int q = atomicAdd(&g_nfixsamp, 1);
            g_fixsamp[q] = b;
        }
    }
}

// apply index fixes: vq_sum adjust, output index, g_idx update
__global__ void fixapply(const float* __restrict__ cb, float* __restrict__ outIdxF) {
    const int nfr = g_nfixrows;
    const int gw = (blockIdx.x * blockDim.x + threadIdx.x) >> 5;
    const int lane = threadIdx.x & 31;
    const int nwarps = (gridDim.x * blockDim.x) >> 5;
    for (int j = gw; j < nfr; j += nwarps) {
        int row = g_fixrows[j];
        int oldid = g_idx[row], newid = g_idx2[row];
        float4 l  = reinterpret_cast<const float4*>(g_lat)[(size_t)row * 32 + lane];
        float4 co = reinterpret_cast<const float4*>(cb)[(size_t)oldid * 32 + lane];
        float4 cn4 = reinterpret_cast<const float4*>(cb)[(size_t)newid * 32 + lane];
        float dx = co.x - l.x, dy = co.y - l.y, dz = co.z - l.z, dw = co.w - l.w;
        float so = dx * dx + dy * dy + dz * dz + dw * dw;
        dx = cn4.x - l.x; dy = cn4.y - l.y; dz = cn4.z - l.z; dw = cn4.w - l.w;
        float sn = dx * dx + dy * dy + dz * dz + dw * dw;
        float d = sn - so;
#pragma unroll
        for (int off = 16; off > 0; off >>= 1) d += __shfl_down_sync(0xffffffffu, d, off);
        if (lane == 0) {
            atomicAdd(&g_vq_sum, d);
            g_idx[row] = newid;
            if (outIdxF) outIdxF[row] = (float)newid;
        }
    }
}

// gather q rows (fp32) for affected samples; zero-pad tail of active tile
__global__ void fixgather(const float* __restrict__ cb) {
    const int ns = g_nfixsamp;
    const int nact = ((ns + 127) >> 7) << 7;
    const int i = blockIdx.x;
    if (i >= nact) return;
    const int tid = threadIdx.x;
    if (i < ns) {
        int b = g_fixsamp[i];
#pragma unroll
        for (int j = 0; j < 8; j++) {
            int k = tid + j * 256;
            int id = g_idx[b * 16 + (k >> 7)];
            g_qfix[(size_t)i * cLAT + k] = cb[(size_t)id * cD + (k & 127)];
        }
    } else {
#pragma unroll
        for (int j = 0; j < 8; j++)
            g_qfix[(size_t)i * cLAT + tid + j * 256] = 0.0f;
    }
}

// scatter corrected g1 rows (splits) for affected samples
__global__ void fixscatter() {
    const int ns = g_nfixsamp;
    const int i = blockIdx.x;
    if (i >= ns) return;
    int b = g_fixsamp[i];
    const int tid = threadIdx.x;
#pragma unroll
    for (int j = 0; j < 2; j++) {
        int u = tid + j * 256;
        reinterpret_cast<uint32_t*>(g_g1H + (size_t)b * cHID)[u] =
            reinterpret_cast<const uint32_t*>(g_gfixH + (size_t)i * cHID)[u];
        reinterpret_cast<uint32_t*>(g_g1L + (size_t)b * cHID)[u] =
            reinterpret_cast<const uint32_t*>(g_gfixL + (size_t)i * cHID)[u];
    }
}

// gather: 64 rows/block, one atomic per block (speculative: uses L1 indices)
__global__ void __launch_bounds__(256)
gather_vq(const float* __restrict__ cb, float* __restrict__ outIdxF) {
    __shared__ float wsum[8];
    const int tid = threadIdx.x;
    const int warp = tid >> 5, lane = tid & 31;
    float s = 0.0f;
#pragma unroll
    for (int it = 0; it < 8; it++) {
        const int row = blockIdx.x * 64 + warp * 8 + it;
        const int id = g_idx[row];
        float4 c = reinterpret_cast<const float4*>(cb)[(size_t)id * 32 + lane];
        float4 l = reinterpret_cast<const float4*>(g_lat)[(size_t)row * 32 + lane];
        if (lane < 16) {
            reinterpret_cast<uint4*>(g_qH + (size_t)row * cD)[lane] =
                reinterpret_cast<const uint4*>(g_cbH + (size_t)id * cD)[lane];
        } else {
            reinterpret_cast<uint4*>(g_qL + (size_t)row * cD)[lane - 16] =
                reinterpret_cast<const uint4*>(g_cbL + (size_t)id * cD)[lane - 16];
        }
        float dx = c.x - l.x, dy = c.y - l.y, dz = c.z - l.z, dw = c.w - l.w;
        s += dx * dx + dy * dy + dz * dz + dw * dw;
        if (lane == 0 && outIdxF) outIdxF[row] = (float)id;
    }
#pragma unroll
    for (int off = 16; off > 0; off >>= 1) s += __shfl_down_sync(0xffffffffu, s, off);
    if (lane == 0) wsum[warp] = s;
    __syncthreads();
    if (tid == 0) {
        float t = 0.0f;
#pragma unroll
        for (int w = 0; w < 8; w++) t += wsum[w];
        atomicAdd(&g_vq_sum, t);
    }
}

__global__ void finalize_k(float* __restrict__ out, int out_size) {
    if (out_size >= FULL_OUT) {
        float m = g_vq_sum / (float)(cB * cN * cD);
        float vq = 1.25f * m;
        float rl = g_recon_sum / (float)RECON_ELEMS;
        out[SCALAR_OFF + 0] = vq;
        out[SCALAR_OFF + 1] = rl;
        out[SCALAR_OFF + 2] = rl + vq;
    }
}

// ---------------- launch ----------------
extern "C" void kernel_launch(void* const* d_in, const int* in_sizes, int n_in,
                              void* d_out, int out_size) {
    const float* actions = (const float*)d_in[0];
    const float* e_w1 = (const float*)d_in[1];
    const float* e_b1 = (const float*)d_in[2];
    const float* e_w2 = (const float*)d_in[3];
    const float* e_b2 = (const float*)d_in[4];
    const float* e_w3 = (const float*)d_in[5];
    const float* e_b3 = (const float*)d_in[6];
    const float* cb   = (const float*)d_in[7];
    const float* d_w1 = (const float*)d_in[8];
    const float* d_b1 = (const float*)d_in[9];
    const float* d_w2 = (const float*)d_in[10];
    const float* d_b2 = (const float*)d_in[11];
    const float* d_w3 = (const float*)d_in[12];
    const float* d_b3 = (const float*)d_in[13];
    float* out = (float*)d_out;

    float *p_h1, *p_h2, *p_lat, *p_qfix, *p_gfix;
    cudaGetSymbolAddress((void**)&p_h1,  g_h1);
    cudaGetSymbolAddress((void**)&p_h2,  g_h2);
    cudaGetSymbolAddress((void**)&p_lat, g_lat);
    cudaGetSymbolAddress((void**)&p_qfix, g_qfix);
    cudaGetSymbolAddress((void**)&p_gfix, g_gfix);
    __half *latH, *latL, *qH, *qL, *g1H, *g1L, *g2H, *g2L, *cbH, *cbL;
    __half *v1H, *v1L, *v2H, *v2L, *v3H, *v3L, *gfH, *gfL;
    cudaGetSymbolAddress((void**)&latH, g_latH); cudaGetSymbolAddress((void**)&latL, g_latL);
    cudaGetSymbolAddress((void**)&qH, g_qH);     cudaGetSymbolAddress((void**)&qL, g_qL);
    cudaGetSymbolAddress((void**)&g1H, g_g1H);   cudaGetSymbolAddress((void**)&g1L, g_g1L);
    cudaGetSymbolAddress((void**)&g2H, g_g2H);   cudaGetSymbolAddress((void**)&g2L, g_g2L);
    cudaGetSymbolAddress((void**)&cbH, g_cbH);   cudaGetSymbolAddress((void**)&cbL, g_cbL);
    cudaGetSymbolAddress((void**)&v1H, g_v1H);   cudaGetSymbolAddress((void**)&v1L, g_v1L);
    cudaGetSymbolAddress((void**)&v2H, g_v2H);   cudaGetSymbolAddress((void**)&v2L, g_v2L);
    cudaGetSymbolAddress((void**)&v3H, g_v3H);   cudaGetSymbolAddress((void**)&v3L, g_v3L);
    cudaGetSymbolAddress((void**)&gfH, g_gfixH); cudaGetSymbolAddress((void**)&gfL, g_gfixL);
    int* pNfixS; cudaGetSymbolAddress((void**)&pNfixS, g_nfixsamp);

    static cudaStream_t s2 = nullptr;
    static cudaEvent_t evFork = nullptr, evA = nullptr, evC = nullptr, evD = nullptr, evL2 = nullptr;
    static bool attr_done = false;
    if (!attr_done) {
        cudaFuncSetAttribute(argmin_l1, cudaFuncAttributeMaxDynamicSharedMemorySize, ARG_SMEM1);
        cudaFuncSetAttribute(argmin_l2, cudaFuncAttributeMaxDynamicSharedMemorySize, ARG_SMEM2);
        cudaFuncSetAttribute((const void*)mma_gemm<1, 1>, cudaFuncAttributeMaxDynamicSharedMemorySize, DEC_SMEM);
        cudaFuncSetAttribute((const void*)mma_gemm<2, 3>, cudaFuncAttributeMaxDynamicSharedMemorySize, DEC_SMEM);
        cudaStreamCreateWithFlags(&s2, cudaStreamNonBlocking);
        cudaEventCreateWithFlags(&evFork, cudaEventDisableTiming);
        cudaEventCreateWithFlags(&evA, cudaEventDisableTiming);
        cudaEventCreateWithFlags(&evC, cudaEventDisableTiming);
        cudaEventCreateWithFlags(&evD, cudaEventDisableTiming);
        cudaEventCreateWithFlags(&evL2, cudaEventDisableTiming);
        attr_done = true;
    }

    const bool has_idx = out_size >= (IDX_OFF + cROWS);
    float* outIdx = has_idx ? (out + IDX_OFF) : nullptr;
    dim3 wt(32, 8);

    // fork: prep chain on s2
    cudaEventRecord(evFork, 0);
    cudaStreamWaitEvent(s2, evFork, 0);
    cn_kernel<<<cK / 8, 256, 0, s2>>>(cb);
    cnmax_kernel<<<1, 256, 0, s2>>>();
    split_act<<<(cK * cD / 4 + 255) / 256, 256, 0, s2>>>(cb, cbH, cbL, cK * cD / 4);
    wsplit<<<dim3(cHID / 32, cLAT / 32), wt, 0, s2>>>(d_w1, v1H, v1L, cLAT, cHID);
    wsplit<<<dim3(cHID / 32, cHID / 32), wt, 0, s2>>>(d_w2, v2H, v2L, cHID, cHID);
    wsplit<<<dim3(cFLAT / 32 + 1, cHID / 32), wt, 0, s2>>>(d_w3, v3H, v3L, cHID, cFLAT);

    // main: encoder (fp32, bit-identical arithmetic); enc3 split into halves
    init_accum<<<cB / 256, 256>>>();
    sgemm_k<1, false><<<dim3(cHID / BN, cB / BM), 256>>>(actions, e_w1, e_b1, p_h1, cB, cHID, cFLAT, nullptr, nullptr, 0, nullptr);
    sgemm_k<1, false><<<dim3(cHID / BN, cB / BM), 256>>>(p_h1, e_w2, e_b2, p_h2, cB, cHID, cHID, nullptr, nullptr, 0, nullptr);
    sgemm_k<0, true><<<dim3(cLAT / BN, cB / BM / 2), 256>>>(p_h2, e_w3, e_b3, p_lat, cB, cLAT, cHID, latH, latL, 0, nullptr);
    cudaEventRecord(evA, 0);

    // s2: first-half argmin L1 overlapped with second-half enc3
    cudaStreamWaitEvent(s2, evA, 0);
    rn_kernel<<<cROWS / 16, 256, 0, s2>>>(0);
    argmin_l1<<<cROWS / 256, 256, ARG_SMEM1, s2>>>(0);
    cudaEventRecord(evC, s2);

    // main: second half enc3 + its L1
    sgemm_k<0, true><<<dim3(cLAT / BN, cB / BM / 2), 256>>>(p_h2, e_w3, e_b3, p_lat, cB, cLAT, cHID, latH, latL, cB / BM / 2, nullptr);
    rn_kernel<<<cROWS / 16, 256>>>(cROWS / 2);
    argmin_l1<<<cROWS / 256, 256, ARG_SMEM1>>>(cROWS / 256);
    cudaEventRecord(evD, 0);
    cudaStreamWaitEvent(0, evC, 0);

    // s2: refinement chain (shadow indices) — concurrent with speculative decode on s0
    cudaStreamWaitEvent(s2, evD, 0);
    argmin_l2<<<dim3(cROWS / 128, L2_PARTS), 256, ARG_SMEM2, s2>>>();
    l2_combine<<<cROWS / 256, 256, 0, s2>>>();
    recheck_k<<<148, 256, 0, s2>>>(cb);
    fixdetect<<<cROWS / 256, 256, 0, s2>>>();
    cudaEventRecord(evL2, s2);

    // s0: speculative gather + decoder layer 1 using L1 indices
    gather_vq<<<cROWS / 64, 256>>>(cb, outIdx);
    mma_gemm<1, 1><<<dim3(cHID / 128, cB / 128), 256, DEC_SMEM>>>(qH, qL, v1H, v1L, d_b1, nullptr, g1H, g1L, cB, cHID, cLAT, nullptr);

    // join refinement; apply fixes
    cudaStreamWaitEvent(0, evL2, 0);
    fixapply<<<32, 256>>>(cb, outIdx);
    fixgather<<<FIXCAP, 256>>>(cb);
    sgemm_k<1, true><<<dim3(cHID / BN, FIXCAP / BM), 256>>>(p_qfix, d_w1, d_b1, p_gfix, FIXCAP, cHID, cLAT, gfH, gfL, 0, pNfixS);
    fixscatter<<<FIXCAP, 256>>>();

    // decoder tail
    mma_gemm<1, 1><<<dim3(cHID / 128, cB / 128), 256, DEC_SMEM>>>(g1H, g1L, v2H, v2L, d_b2, nullptr, g2H, g2L, cB, cHID, cHID, nullptr);
    mma_gemm<2, 3><<<dim3(1, cB / 128), 256, DEC_SMEM>>>(g2H, g2L, v3H, v3L, d_b3, out, nullptr, nullptr, cB, cFLAT, cHID, actions);

    finalize_k<<<1, 1>>>(out, out_size);
}

// round 16
// speedup vs baseline: 1.0247x; 1.0247x over previous
#include <cuda_runtime.h>
#include <cuda_fp16.h>
#include <math.h>
#include <stdint.h>

#define BM 128
#define BN 128
#define BKd 8
#define TM 8
#define TN 8

static constexpr int cB    = 4096;
static constexpr int cT    = 32;
static constexpr int cA    = 3;
static constexpr int cFLAT = 96;
static constexpr int cHID  = 1024;
static constexpr int cD    = 128;
static constexpr int cN    = 16;
static constexpr int cK    = 4096;
static constexpr int cLAT  = 2048;
static constexpr int cROWS = cB * cN;               // 65536
static constexpr int RECON_ELEMS = cB * cT * cA;    // 393216
static constexpr int IDX_OFF     = RECON_ELEMS;
static constexpr int SCALAR_OFF  = IDX_OFF + cROWS;
static constexpr int FULL_OUT    = SCALAR_OFF + 3;

static constexpr float SSCALE   = 256.0f;
static constexpr float LOSCALE  = 2048.0f;
static constexpr float INV_LO   = 4.8828125e-4f;     // 2^-11
static constexpr float INV_FULL = 1.52587890625e-5f; // 2^-16
static constexpr float EPS_SCALED = 2e-7f * 65536.0f;

static constexpr int L2_PARTS = 4;
static constexpr int L2_TILES_PER_PART = (cK / 128) / L2_PARTS;  // 8

// ---------------- scratch ----------------
__device__ float g_h1 [cB * cHID];
__device__ float g_h2 [cB * cHID];
__device__ float g_lat[cB * cLAT];
__device__ float g_cn [cK];
__device__ float g_rn [cROWS];
__device__ int   g_idx[cROWS];
__device__ float g_vq_sum;
__device__ float g_recon_sum;
__device__ int   g_flagcnt;
__device__ int   g_flagrows[cROWS];
__device__ int   g_flagcnt2;
__device__ int   g_flagrows2[cROWS];
__device__ float g_cnmax;
__device__ float g_l2v[cROWS * L2_PARTS];
__device__ float g_l2s[cROWS * L2_PARTS];
__device__ int   g_l2i[cROWS * L2_PARTS];

__device__ __half g_latH[cROWS * cD], g_latL[cROWS * cD];
__device__ __half g_qH [cB * cLAT],   g_qL [cB * cLAT];
__device__ __half g_g1H[cB * cHID],   g_g1L[cB * cHID];
__device__ __half g_g2H[cB * cHID],   g_g2L[cB * cHID];
__device__ __half g_cbH[cK * cD],     g_cbL[cK * cD];
__device__ __half g_v1H[cHID * cLAT],  g_v1L[cHID * cLAT];
__device__ __half g_v2H[cHID * cHID],  g_v2L[cHID * cHID];
__device__ __half g_v3H[cFLAT * cHID], g_v3L[cFLAT * cHID];

// ---------------- low-level helpers ----------------
typedef unsigned long long u64;
__device__ __forceinline__ u64 pack2(float lo, float hi) {
    u64 r;
    asm("mov.b64 %0, {%1, %2};" : "=l"(r) : "r"(__float_as_uint(lo)), "r"(__float_as_uint(hi)));
    return r;
}
__device__ __forceinline__ void fma2(u64 &d, u64 a, u64 b) {
    asm("fma.rn.f32x2 %0, %1, %2, %0;" : "+l"(d) : "l"(a), "l"(b));
}
__device__ __forceinline__ void unpack2(u64 v, float &lo, float &hi) {
    unsigned int l, h;
    asm("mov.b64 {%0, %1}, %2;" : "=r"(l), "=r"(h) : "l"(v));
    lo = __uint_as_float(l); hi = __uint_as_float(h);
}

__device__ __forceinline__ float silu_f(float x) {
    float s;
    if (x >= 0.0f) s = 1.0f / (1.0f + expf(-x));
    else { float e = expf(x); s = e / (1.0f + e); }
    return x * s;
}

__device__ __forceinline__ void mma16816(float c[4], uint32_t a0, uint32_t a1,
                                         uint32_t a2, uint32_t a3,
                                         uint32_t b0, uint32_t b1) {
    asm volatile(
        "mma.sync.aligned.m16n8k16.row.col.f32.f16.f16.f32 "
        "{%0,%1,%2,%3},{%4,%5,%6,%7},{%8,%9},{%0,%1,%2,%3};"
        : "+f"(c[0]), "+f"(c[1]), "+f"(c[2]), "+f"(c[3])
        : "r"(a0), "r"(a1), "r"(a2), "r"(a3), "r"(b0), "r"(b1));
}

__device__ __forceinline__ void ldsm4(uint32_t r[4], uint32_t addr) {
    asm volatile("ldmatrix.sync.aligned.m8n8.x4.shared.b16 {%0,%1,%2,%3}, [%4];"
                 : "=r"(r[0]), "=r"(r[1]), "=r"(r[2]), "=r"(r[3]) : "r"(addr));
}

__device__ __forceinline__ void cp_async16(void* dst, const void* src) {
    uint32_t d = (uint32_t)__cvta_generic_to_shared(dst);
    asm volatile("cp.async.cg.shared.global [%0], [%1], 16;" :: "r"(d), "l"(src));
}
#define CP_COMMIT() asm volatile("cp.async.commit_group;" ::: "memory")
#define CP_WAIT2()  asm volatile("cp.async.wait_group 2;" ::: "memory")

__global__ void init_accum() {
    g_vq_sum = 0.0f; g_recon_sum = 0.0f; g_flagcnt = 0; g_flagcnt2 = 0;
}

__global__ void cn_kernel(const float* __restrict__ cb) {
    int warp = (blockIdx.x * blockDim.x + threadIdx.x) >> 5;
    int lane = threadIdx.x & 31;
    if (warp >= cK) return;
    const float4 v = reinterpret_cast<const float4*>(cb)[warp * 32 + lane];
    double a = (double)v.x * v.x + (double)v.y * v.y + (double)v.z * v.z + (double)v.w * v.w;
#pragma unroll
    for (int off = 16; off > 0; off >>= 1) a += __shfl_down_sync(0xffffffffu, a, off);
    if (lane == 0) g_cn[warp] = (float)a;
}

__global__ void cnmax_kernel() {
    __shared__ float red[256];
    float m = 0.0f;
    for (int i = threadIdx.x; i < cK; i += 256) m = fmaxf(m, g_cn[i]);
    red[threadIdx.x] = m;
    __syncthreads();
    for (int s = 128; s > 0; s >>= 1) {
        if (threadIdx.x < s) red[threadIdx.x] = fmaxf(red[threadIdx.x], red[threadIdx.x + s]);
        __syncthreads();
    }
    if (threadIdx.x == 0) g_cnmax = sqrtf(red[0]);
}

__global__ void rn_kernel(int rowoff) {
    int warp = rowoff + ((blockIdx.x * blockDim.x + threadIdx.x) >> 5);
    int lane = threadIdx.x & 31;
    if (warp >= cROWS) return;
    const float4 v = reinterpret_cast<const float4*>(g_lat)[(size_t)warp * 32 + lane];
    double a = (double)v.x * v.x + (double)v.y * v.y + (double)v.z * v.z + (double)v.w * v.w;
#pragma unroll
    for (int off = 16; off > 0; off >>= 1) a += __shfl_down_sync(0xffffffffu, a, off);
    if (lane == 0) g_rn[warp] = (float)a;
}

__global__ void split_act(const float* __restrict__ src, __half* __restrict__ hi,
                          __half* __restrict__ lo, int n4) {
    int i = blockIdx.x * blockDim.x + threadIdx.x;
    if (i >= n4) return;
    float4 v = reinterpret_cast<const float4*>(src)[i];
    float x0 = v.x * SSCALE, x1 = v.y * SSCALE, x2 = v.z * SSCALE, x3 = v.w * SSCALE;
    __half h0 = __float2half_rn(x0), h1 = __float2half_rn(x1);
    __half h2 = __float2half_rn(x2), h3 = __float2half_rn(x3);
    __half2* hp = reinterpret_cast<__half2*>(hi);
    hp[i * 2 + 0] = __half2(h0, h1);
    hp[i * 2 + 1] = __half2(h2, h3);
    __half2* lp = reinterpret_cast<__half2*>(lo);
    lp[i * 2 + 0] = __half2(__float2half_rn((x0 - __half2float(h0)) * LOSCALE),
                            __float2half_rn((x1 - __half2float(h1)) * LOSCALE));
    lp[i * 2 + 1] = __half2(__float2half_rn((x2 - __half2float(h2)) * LOSCALE),
                            __float2half_rn((x3 - __half2float(h3)) * LOSCALE));
}

__global__ void wsplit(const float* __restrict__ W, __half* __restrict__ WtH,
                       __half* __restrict__ WtL, int Kd, int N) {
    __shared__ float tile[32][33];
    const int bx = blockIdx.x * 32, by = blockIdx.y * 32;
    const int tx = threadIdx.x, ty = threadIdx.y;
    for (int r = ty; r < 32; r += 8) {
        int n = bx + tx;
        tile[r][tx] = (n < N) ? W[(size_t)(by + r) * N + n] : 0.0f;
    }
    __syncthreads();
    for (int r = ty; r < 32; r += 8) {
        int n = bx + r, k = by + tx;
        if (n < N) {
            float x = tile[tx][r] * SSCALE;
            __half h = __float2half_rn(x);
            WtH[(size_t)n * Kd + k] = h;
            WtL[(size_t)n * Kd + k] = __float2half_rn((x - __half2float(h)) * LOSCALE);
        }
    }
}

// ---------------- fp32 SGEMM (f32x2) — encoder (bit-identical path) ----------------
template <int MODE, bool SPLITOUT>
__global__ void __launch_bounds__(256)
sgemm_k(const float* __restrict__ Ag, const float* __restrict__ Bg,
        const float* __restrict__ bias, float* __restrict__ Cg,
        int M, int N, int Kd, __half* __restrict__ hiP, __half* __restrict__ loP,
        int yoff) {
    __shared__ float As[2][BKd][BM];
    __shared__ float Bs[2][BKd][BN];
    const int tid = threadIdx.x;
    const int rbase = (blockIdx.y + yoff) * BM, cbase = blockIdx.x * BN;
    const int rowA = tid >> 1, colA4 = (tid & 1) * 4;
    const int rowB = tid >> 5, colB4 = (tid & 31) * 4;
    const int tr = (tid >> 4) * TM, tc = (tid & 15) * TN;

    u64 acc[TM][TN / 2];
#pragma unroll
    for (int i = 0; i < TM; i++)
#pragma unroll
        for (int j = 0; j < TN / 2; j++) acc[i][j] = 0ull;

    const int nt = Kd / BKd;
    const bool bok = (cbase + colB4 < N);

    {
        float4 pa = *reinterpret_cast<const float4*>(&Ag[(size_t)(rbase + rowA) * Kd + colA4]);
        float4 pb = make_float4(0.f, 0.f, 0.f, 0.f);
        if (bok) pb = *reinterpret_cast<const float4*>(&Bg[(size_t)rowB * N + cbase + colB4]);
        As[0][colA4 + 0][rowA] = pa.x; As[0][colA4 + 1][rowA] = pa.y;
        As[0][colA4 + 2][rowA] = pa.z; As[0][colA4 + 3][rowA] = pa.w;
        *reinterpret_cast<float4*>(&Bs[0][rowB][colB4]) = pb;
    }

    for (int t = 0; t < nt; t++) {
        const int cur = t & 1;
        float4 pa, pb;
        const bool more = (t + 1 < nt);
        if (more) {
            pa = *reinterpret_cast<const float4*>(
                &Ag[(size_t)(rbase + rowA) * Kd + (t + 1) * BKd + colA4]);
            pb = make_float4(0.f, 0.f, 0.f, 0.f);
            if (bok)
                pb = *reinterpret_cast<const float4*>(
                    &Bg[(size_t)((t + 1) * BKd + rowB) * N + cbase + colB4]);
        }
        __syncthreads();
#pragma unroll
        for (int k = 0; k < BKd; k++) {
            float4 a0 = *reinterpret_cast<const float4*>(&As[cur][k][tr]);
            float4 a1 = *reinterpret_cast<const float4*>(&As[cur][k][tr + 4]);
            const u64* bp = reinterpret_cast<const u64*>(&Bs[cur][k][tc]);
            u64 b0 = bp[0], b1 = bp[1], b2 = bp[2], b3 = bp[3];
            float am[TM] = {a0.x, a0.y, a0.z, a0.w, a1.x, a1.y, a1.z, a1.w};
#pragma unroll
            for (int i = 0; i < TM; i++) {
                u64 ap = pack2(am[i], am[i]);
                fma2(acc[i][0], ap, b0); fma2(acc[i][1], ap, b1);
                fma2(acc[i][2], ap, b2); fma2(acc[i][3], ap, b3);
            }
        }
        if (more) {
            const int nxt = cur ^ 1;
            As[nxt][colA4 + 0][rowA] = pa.x; As[nxt][colA4 + 1][rowA] = pa.y;
            As[nxt][colA4 + 2][rowA] = pa.z; As[nxt][colA4 + 3][rowA] = pa.w;
            *reinterpret_cast<float4*>(&Bs[nxt][rowB][colB4]) = pb;
        }
    }

#pragma unroll
    for (int i = 0; i < TM; i++) {
        const int row = rbase + tr + i;
#pragma unroll
        for (int j = 0; j < TN / 2; j++) {
            const int c0 = cbase + tc + 2 * j;
            if (c0 < N) {
                float lo, hi; unpack2(acc[i][j], lo, hi);
                float v0 = lo + bias[c0], v1 = hi + bias[c0 + 1];
                if (MODE == 1) { v0 = silu_f(v0); v1 = silu_f(v1); }
                Cg[(size_t)row * N + c0]     = v0;
                Cg[(size_t)row * N + c0 + 1] = v1;
                if (SPLITOUT) {
                    float x0 = v0 * SSCALE, x1 = v1 * SSCALE;
                    __half h0 = __float2half_rn(x0), h1 = __float2half_rn(x1);
                    *reinterpret_cast<__half2*>(&hiP[(size_t)row * N + c0]) = __half2(h0, h1);
                    *reinterpret_cast<__half2*>(&loP[(size_t)row * N + c0]) =
                        __half2(__float2half_rn((x0 - __half2float(h0)) * LOSCALE),
                                __float2half_rn((x1 - __half2float(h1)) * LOSCALE));
                }
            }
        }
    }
}

// ---------------- split-fp16 HMMA GEMM — decoder ----------------
static constexpr int KP   = 40;
static constexpr int STG  = 128 * KP;
static constexpr int DEC_SMEM = 4 * 2 * STG * 2;  // 81920 bytes

template <int MODE, int PASSES>
__global__ void __launch_bounds__(256)
mma_gemm(const __half* __restrict__ Ah, const __half* __restrict__ Al,
         const __half* __restrict__ Bh, const __half* __restrict__ Bl,
         const float* __restrict__ bias, float* __restrict__ Cg,
         __half* __restrict__ hiP, __half* __restrict__ loP,
         int M, int N, int Kd, const float* __restrict__ ref) {
    extern __shared__ __align__(16) __half dsm[];
    __half* As = dsm;
    __half* Bs = dsm + 4 * STG;

    const int tid = threadIdx.x;
    const int lane = tid & 31, warp = tid >> 5;
    const int wm = warp >> 2, wn = warp & 3;
    const int gq = lane >> 2, tq = lane & 3;
    const int rbase = blockIdx.y * 128, cbase = blockIdx.x * 128;

    const int KC = Kd >> 5;
    const int NCH = PASSES * KC;
    const int RESC = (PASSES > 1) ? (PASSES - 1) * KC : -1;

    if (N < 128) {
        const uint4 z4 = make_uint4(0, 0, 0, 0);
        for (int i = tid; i < 4 * STG / 8; i += 256)
            *reinterpret_cast<uint4*>(Bs + i * 8) = z4;
    }

    float acc[4][4][4];
#pragma unroll
    for (int a = 0; a < 4; a++)
#pragma unroll
        for (int b = 0; b < 4; b++)
#pragma unroll
            for (int c = 0; c < 4; c++) acc[a][b][c] = 0.0f;

    auto loadAB = [&](int c, int st) {
        const int p = c / KC, kc = c % KC;
        const __half* Asrc = (PASSES == 3 && p == 1) ? Al : Ah;
        const __half* Bsrc = (PASSES > 1 && p == 0) ? Bl : Bh;
#pragma unroll
        for (int j = 0; j < 2; j++) {
            int i = tid + 256 * j;
            int row = i >> 2, seg = i & 3;
            cp_async16(As + st * STG + row * KP + seg * 8,
                       Asrc + (size_t)(rbase + row) * Kd + kc * 32 + seg * 8);
            int col = cbase + row;
            if (col < N)
                cp_async16(Bs + st * STG + row * KP + seg * 8,
                           Bsrc + (size_t)col * Kd + kc * 32 + seg * 8);
        }
    };

    const uint32_t aRow = (lane & 7) + ((lane >> 3) & 1) * 8;
    const uint32_t aK   = (lane >> 4) * 8;
    const uint32_t bRow = ((lane >> 4) & 1) * 8 + (lane & 7);
    const uint32_t bK   = ((lane >> 3) & 1) * 8;
    const uint32_t aBase0 = (uint32_t)__cvta_generic_to_shared(As) +
                            ((wm * 64 + aRow) * KP + aK) * 2;
    const uint32_t bBase0 = (uint32_t)__cvta_generic_to_shared(Bs) +
                            ((wn * 32 + bRow) * KP + bK) * 2;

    loadAB(0, 0); CP_COMMIT();
    loadAB(1, 1); CP_COMMIT();
    for (int c = 0; c < NCH; c++) {
        if (c + 2 < NCH) loadAB(c + 2, (c + 2) & 3);
        CP_COMMIT();
        CP_WAIT2();
        __syncthreads();
        if (PASSES > 1 && c == RESC) {
#pragma unroll
            for (int a = 0; a < 4; a++)
#pragma unroll
                for (int b = 0; b < 4; b++)
#pragma unroll
                    for (int q = 0; q < 4; q++) acc[a][b][q] *= INV_LO;
        }
        const uint32_t aSt = aBase0 + ((c & 3) * STG) * 2;
        const uint32_t bSt = bBase0 + ((c & 3) * STG) * 2;
#pragma unroll
        for (int ks = 0; ks < 2; ks++) {
            const int k0 = ks * 16;
            uint32_t af[4][4];
#pragma unroll
            for (int mt = 0; mt < 4; mt++)
                ldsm4(af[mt], aSt + (mt * 16 * KP + k0) * 2);
            uint32_t bf[2][4];
#pragma unroll
            for (int pr = 0; pr < 2; pr++)
                ldsm4(bf[pr], bSt + (pr * 16 * KP + k0) * 2);
#pragma unroll
            for (int nt = 0; nt < 4; nt++) {
                uint32_t b0 = bf[nt >> 1][(nt & 1) * 2 + 0];
                uint32_t b1 = bf[nt >> 1][(nt & 1) * 2 + 1];
#pragma unroll
                for (int mt = 0; mt < 4; mt++)
                    mma16816(acc[mt][nt], af[mt][0], af[mt][1], af[mt][2], af[mt][3], b0, b1);
            }
        }
    }

    float lsum = 0.0f;
#pragma unroll
    for (int mt = 0; mt < 4; mt++) {
#pragma unroll
        for (int nt = 0; nt < 4; nt++) {
            const int row0 = rbase + wm * 64 + mt * 16 + gq;
            const int col0 = cbase + wn * 32 + nt * 8 + tq * 2;
            if (col0 < N) {
                const float bz0 = bias[col0], bz1 = bias[col0 + 1];
#pragma unroll
                for (int h = 0; h < 2; h++) {
                    const int row = row0 + 8 * h;
                    float v0 = acc[mt][nt][2 * h + 0] * INV_FULL + bz0;
                    float v1 = acc[mt][nt][2 * h + 1] * INV_FULL + bz1;
                    if (MODE == 1) {
                        v0 = silu_f(v0); v1 = silu_f(v1);
                        float x0 = v0 * SSCALE, x1 = v1 * SSCALE;
                        __half h0 = __float2half_rn(x0), h1 = __float2half_rn(x1);
                        *reinterpret_cast<__half2*>(&hiP[(size_t)row * N + col0]) = __half2(h0, h1);
                        *reinterpret_cast<__half2*>(&loP[(size_t)row * N + col0]) =
                            __half2(__float2half_rn((x0 - __half2float(h0)) * LOSCALE),
                                    __float2half_rn((x1 - __half2float(h1)) * LOSCALE));
                    } else {
                        Cg[(size_t)row * N + col0]     = v0;
                        Cg[(size_t)row * N + col0 + 1] = v1;
                        float d0 = v0 - ref[(size_t)row * N + col0];
                        float d1 = v1 - ref[(size_t)row * N + col0 + 1];
                        lsum = fmaf(d0, d0, fmaf(d1, d1, lsum));
                    }
                }
            }
        }
    }
    if (MODE == 2) {
        __shared__ float red[256];
        red[tid] = lsum; __syncthreads();
        for (int s = 128; s > 0; s >>= 1) { if (tid < s) red[tid] += red[tid + s]; __syncthreads(); }
        if (tid == 0) atomicAdd(&g_recon_sum, red[0]);
    }
}

// ---------------- Level-1 HMMA argmin — hi-only + sound flag ----------------
static constexpr int KPA = 136;
static constexpr int KPB = 40;
static constexpr int B_STGH = 128 * KPB;
static constexpr int ARG_SMEM1 =
    (128 * KPA + 4 * B_STGH) * 2 + (cK + 512 * 3) * 4;   // 98304

__global__ void __launch_bounds__(256)
argmin_l1(int boff) {
    extern __shared__ __align__(16) __half dsm[];
    __half* a_h = dsm;
    __half* bs  = dsm + 128 * KPA;
    float*  cn_s = reinterpret_cast<float*>(dsm + 128 * KPA + 4 * B_STGH);
    float*  RV = cn_s + cK;
    float*  RS = RV + 512;
    int*    RI = reinterpret_cast<int*>(RS + 512);

    const int tid = threadIdx.x;
    const int lane = tid & 31, warp = tid >> 5;
    const int wm = warp >> 2, wn = warp & 3;
    const int gq = lane >> 2, tq = lane & 3;
    const int rbase = (blockIdx.x + boff) * 128;

#pragma unroll
    for (int j = 0; j < 8; j++) {
        int i = tid + 256 * j;
        int row = i >> 4, seg = i & 15;
        *reinterpret_cast<uint4*>(a_h + row * KPA + seg * 8) =
            *reinterpret_cast<const uint4*>(g_latH + (size_t)(rbase + row) * cD + seg * 8);
    }
    for (int i = tid; i < cK / 4; i += 256) {
        float4 v = reinterpret_cast<const float4*>(g_cn)[i];
        v.x *= 65536.0f; v.y *= 65536.0f; v.z *= 65536.0f; v.w *= 65536.0f;
        reinterpret_cast<float4*>(cn_s)[i] = v;
    }

    float rnr[4][2];
#pragma unroll
    for (int mt = 0; mt < 4; mt++)
#pragma unroll
        for (int h = 0; h < 2; h++)
            rnr[mt][h] = g_rn[rbase + wm * 64 + mt * 16 + gq + 8 * h] * 65536.0f;

    float bv[4][2], sv[4][2];
    int   bi[4][2];
#pragma unroll
    for (int mt = 0; mt < 4; mt++)
#pragma unroll
        for (int h = 0; h < 2; h++) { bv[mt][h] = INFINITY; sv[mt][h] = INFINITY; bi[mt][h] = 0; }

    float acc[4][4][4];
#pragma unroll
    for (int a = 0; a < 4; a++)
#pragma unroll
        for (int b = 0; b < 4; b++)
#pragma unroll
            for (int q = 0; q < 4; q++) acc[a][b][q] = 0.0f;

    auto loadB = [&](int c, int st) {
        const int ct = c >> 2, kc = c & 3;
#pragma unroll
        for (int j = 0; j < 2; j++) {
            int i = tid + 256 * j;
            int row = i >> 2, seg = i & 3;
            cp_async16(bs + st * B_STGH + row * KPB + seg * 8,
                       g_cbH + (size_t)(ct * 128 + row) * cD + kc * 32 + seg * 8);
        }
    };

    const uint32_t aRow = (lane & 7) + ((lane >> 3) & 1) * 8;
    const uint32_t aK   = (lane >> 4) * 8;
    const uint32_t bRow = ((lane >> 4) & 1) * 8 + (lane & 7);
    const uint32_t bK   = ((lane >> 3) & 1) * 8;
    const uint32_t aBaseH = (uint32_t)__cvta_generic_to_shared(a_h) +
                            ((wm * 64 + aRow) * KPA + aK) * 2;
    const uint32_t bBase0 = (uint32_t)__cvta_generic_to_shared(bs) +
                            ((wn * 32 + bRow) * KPB + bK) * 2;

    const int NCHT = 32 * 4;
    loadB(0, 0); CP_COMMIT();
    loadB(1, 1); CP_COMMIT();
    for (int c = 0; c < NCHT; c++) {
        if (c + 2 < NCHT) loadB(c + 2, (c + 2) & 3);
        CP_COMMIT();
        CP_WAIT2();
        __syncthreads();
        const int kcc = c & 3;
        const uint32_t bSt = bBase0 + ((c & 3) * B_STGH) * 2;
#pragma unroll
        for (int ks = 0; ks < 2; ks++) {
            const int k0 = kcc * 32 + ks * 16;
            uint32_t af[4][4];
#pragma unroll
            for (int mt = 0; mt < 4; mt++)
                ldsm4(af[mt], aBaseH + (mt * 16 * KPA + k0) * 2);
            uint32_t bf[2][4];
#pragma unroll
            for (int pr = 0; pr < 2; pr++)
                ldsm4(bf[pr], bSt + (pr * 16 * KPB + ks * 16) * 2);
#pragma unroll
            for (int nt = 0; nt < 4; nt++) {
                uint32_t b0 = bf[nt >> 1][(nt & 1) * 2 + 0];
                uint32_t b1 = bf[nt >> 1][(nt & 1) * 2 + 1];
#pragma unroll
                for (int mt = 0; mt < 4; mt++)
                    mma16816(acc[mt][nt], af[mt][0], af[mt][1], af[mt][2], af[mt][3], b0, b1);
            }
        }
        if (kcc == 3) {
            const int ct = c >> 2;
#pragma unroll
            for (int mt = 0; mt < 4; mt++) {
#pragma unroll
                for (int nt = 0; nt < 4; nt++) {
                    const int col0 = ct * 128 + wn * 32 + nt * 8 + tq * 2;
#pragma unroll
                    for (int h = 0; h < 2; h++) {
#pragma unroll
                        for (int cc = 0; cc < 2; cc++) {
                            const int kg = col0 + cc;
                            float s1 = __fadd_rn(rnr[mt][h], cn_s[kg]);
                            float d  = __fadd_rn(s1, -2.0f * acc[mt][nt][2 * h + cc]);
                            if (d < bv[mt][h] || (d == bv[mt][h] && kg < bi[mt][h])) {
                                sv[mt][h] = bv[mt][h]; bv[mt][h] = d; bi[mt][h] = kg;
                            } else if (d < sv[mt][h]) {
                                sv[mt][h] = d;
                            }
                        }
                    }
                    acc[mt][nt][0] = 0.0f; acc[mt][nt][1] = 0.0f;
                    acc[mt][nt][2] = 0.0f; acc[mt][nt][3] = 0.0f;
                }
            }
        }
    }

#pragma unroll
    for (int mt = 0; mt < 4; mt++) {
#pragma unroll
        for (int h = 0; h < 2; h++) {
            float b = bv[mt][h], s = sv[mt][h];
            int   i = bi[mt][h];
#pragma unroll
            for (int m = 1; m <= 2; m <<= 1) {
                float b2 = __shfl_xor_sync(0xffffffffu, b, m);
                float s2 = __shfl_xor_sync(0xffffffffu, s, m);
                int   i2 = __shfl_xor_sync(0xffffffffu, i, m);
                if (b2 < b || (b2 == b && i2 < i)) { s = fminf(b, s2); b = b2; i = i2; }
                else s = fminf(s, b2);
            }
            if (tq == 0) {
                const int rl = wm * 64 + mt * 16 + gq + 8 * h;
                RV[rl * 4 + wn] = b; RS[rl * 4 + wn] = s; RI[rl * 4 + wn] = i;
            }
        }
    }
    __syncthreads();
    if (tid < 128) {
        float b = RV[tid * 4], s = RS[tid * 4];
        int   i = RI[tid * 4];
#pragma unroll
        for (int w = 1; w < 4; w++) {
            float b2 = RV[tid * 4 + w], s2 = RS[tid * 4 + w];
            int   i2 = RI[tid * 4 + w];
            if (b2 < b || (b2 == b && i2 < i)) { s = fminf(b, s2); b = b2; i = i2; }
            else s = fminf(s, b2);
        }
        g_idx[rbase + tid] = i;
        // sound flag: rigorous bound 64*sqrt(rn)*cmax; keep 1.125x margin + abs slack
        float thr = 72.0f * sqrtf(g_rn[rbase + tid]) * g_cnmax + 0.01f;
        if (s - b < thr) {
            int p = atomicAdd(&g_flagcnt, 1);
            g_flagrows[p] = rbase + tid;
        }
    }
}

// ---------------- Level-2 HMMA argmin — 3-pass, code-partitioned ----------------
static constexpr int ARG_SMEM2 =
    (256 * KPA + 4 * B_STGH) * 2 + (cK + 512 * 3) * 4 + 512;   // ~133.6KB

__global__ void __launch_bounds__(256)
argmin_l2() {
    extern __shared__ __align__(16) __half dsm[];
    __half* a_h = dsm;
    __half* a_l = dsm + 128 * KPA;
    __half* bs  = dsm + 256 * KPA;
    float*  cn_s = reinterpret_cast<float*>(dsm + 256 * KPA + 4 * B_STGH);
    float*  RV = cn_s + cK;
    float*  RS = RV + 512;
    int*    RI = reinterpret_cast<int*>(RS + 512);
    int*    rid_s = RI + 512;

    const int nf = g_flagcnt;
    const int ntiles = (nf + 127) >> 7;
    if ((int)blockIdx.x >= ntiles) return;

    const int tid = threadIdx.x;
    const int lane = tid & 31, warp = tid >> 5;
    const int wm = warp >> 2, wn = warp & 3;
    const int gq = lane >> 2, tq = lane & 3;
    const int base = blockIdx.x * 128;
    const int part = blockIdx.y;
    const int ct0 = part * L2_TILES_PER_PART;

    if (tid < 128) {
        int f = base + tid;
        rid_s[tid] = g_flagrows[(f < nf) ? f : (nf - 1)];
    }
    __syncthreads();

#pragma unroll
    for (int j = 0; j < 8; j++) {
        int i = tid + 256 * j;
        int row = i >> 4, seg = i & 15;
        int ridx = rid_s[row];
        *reinterpret_cast<uint4*>(a_h + row * KPA + seg * 8) =
            *reinterpret_cast<const uint4*>(g_latH + (size_t)ridx * cD + seg * 8);
        *reinterpret_cast<uint4*>(a_l + row * KPA + seg * 8) =
            *reinterpret_cast<const uint4*>(g_latL + (size_t)ridx * cD + seg * 8);
    }
    for (int i = tid; i < cK / 4; i += 256) {
        float4 v = reinterpret_cast<const float4*>(g_cn)[i];
        v.x *= 65536.0f; v.y *= 65536.0f; v.z *= 65536.0f; v.w *= 65536.0f;
        reinterpret_cast<float4*>(cn_s)[i] = v;
    }

    float rnr[4][2];
#pragma unroll
    for (int mt = 0; mt < 4; mt++)
#pragma unroll
        for (int h = 0; h < 2; h++)
            rnr[mt][h] = g_rn[rid_s[wm * 64 + mt * 16 + gq + 8 * h]] * 65536.0f;

    float bv[4][2], sv[4][2];
    int   bi[4][2];
#pragma unroll
    for (int mt = 0; mt < 4; mt++)
#pragma unroll
        for (int h = 0; h < 2; h++) { bv[mt][h] = INFINITY; sv[mt][h] = INFINITY; bi[mt][h] = 0; }

    float acc[4][4][4];
#pragma unroll
    for (int a = 0; a < 4; a++)
#pragma unroll
        for (int b = 0; b < 4; b++)
#pragma unroll
            for (int q = 0; q < 4; q++) acc[a][b][q] = 0.0f;

    auto loadB = [&](int c, int st) {
        const int ct = ct0 + c / 12, sub = c % 12;
        const __half* src = ((sub >> 2) == 0) ? g_cbL : g_cbH;
        const int kc = sub & 3;
#pragma unroll
        for (int j = 0; j < 2; j++) {
            int i = tid + 256 * j;
            int row = i >> 2, seg = i & 3;
            cp_async16(bs + st * B_STGH + row * KPB + seg * 8,
                       src + (size_t)(ct * 128 + row) * cD + kc * 32 + seg * 8);
        }
    };

    const uint32_t aRow = (lane & 7) + ((lane >> 3) & 1) * 8;
    const uint32_t aK   = (lane >> 4) * 8;
    const uint32_t bRow = ((lane >> 4) & 1) * 8 + (lane & 7);
    const uint32_t bK   = ((lane >> 3) & 1) * 8;
    const uint32_t aBaseH = (uint32_t)__cvta_generic_to_shared(a_h) +
                            ((wm * 64 + aRow) * KPA + aK) * 2;
    const uint32_t aBaseL = (uint32_t)__cvta_generic_to_shared(a_l) +
                            ((wm * 64 + aRow) * KPA + aK) * 2;
    const uint32_t bBase0 = (uint32_t)__cvta_generic_to_shared(bs) +
                            ((wn * 32 + bRow) * KPB + bK) * 2;

    const int NCHT = L2_TILES_PER_PART * 12;   // 96
    loadB(0, 0); CP_COMMIT();
    loadB(1, 1); CP_COMMIT();
    for (int c = 0; c < NCHT; c++) {
        if (c + 2 < NCHT) loadB(c + 2, (c + 2) & 3);
        CP_COMMIT();
        CP_WAIT2();
        __syncthreads();
        const int sub = c % 12;
        if (sub == 8) {
#pragma unroll
            for (int a = 0; a < 4; a++)
#pragma unroll
                for (int b = 0; b < 4; b++)
#pragma unroll
                    for (int q = 0; q < 4; q++) acc[a][b][q] *= INV_LO;
        }
        const int kcc = sub & 3;
        const uint32_t aBase = ((sub >> 2) == 1) ? aBaseL : aBaseH;
        const uint32_t bSt = bBase0 + ((c & 3) * B_STGH) * 2;
#pragma unroll
        for (int ks = 0; ks < 2; ks++) {
            const int k0 = kcc * 32 + ks * 16;
            uint32_t af[4][4];
#pragma unroll
            for (int mt = 0; mt < 4; mt++)
                ldsm4(af[mt], aBase + (mt * 16 * KPA + k0) * 2);
            uint32_t bf[2][4];
#pragma unroll
            for (int pr = 0; pr < 2; pr++)
                ldsm4(bf[pr], bSt + (pr * 16 * KPB + ks * 16) * 2);
#pragma unroll
            for (int nt = 0; nt < 4; nt++) {
                uint32_t b0 = bf[nt >> 1][(nt & 1) * 2 + 0];
                uint32_t b1 = bf[nt >> 1][(nt & 1) * 2 + 1];
#pragma unroll
                for (int mt = 0; mt < 4; mt++)
                    mma16816(acc[mt][nt], af[mt][0], af[mt][1], af[mt][2], af[mt][3], b0, b1);
            }
        }
        if (sub == 11) {
            const int ct = ct0 + c / 12;
#pragma unroll
            for (int mt = 0; mt < 4; mt++) {
#pragma unroll
                for (int nt = 0; nt < 4; nt++) {
                    const int col0 = ct * 128 + wn * 32 + nt * 8 + tq * 2;
#pragma unroll
                    for (int h = 0; h < 2; h++) {
#pragma unroll
                        for (int cc = 0; cc < 2; cc++) {
                            const int kg = col0 + cc;
                            float s1 = __fadd_rn(rnr[mt][h], cn_s[kg]);
                            float d  = __fadd_rn(s1, -2.0f * acc[mt][nt][2 * h + cc]);
                            if (d < bv[mt][h] || (d == bv[mt][h] && kg < bi[mt][h])) {
                                sv[mt][h] = bv[mt][h]; bv[mt][h] = d; bi[mt][h] = kg;
                            } else if (d < sv[mt][h]) {
                                sv[mt][h] = d;
                            }
                        }
                    }
                    acc[mt][nt][0] = 0.0f; acc[mt][nt][1] = 0.0f;
                    acc[mt][nt][2] = 0.0f; acc[mt][nt][3] = 0.0f;
                }
            }
        }
    }

#pragma unroll
    for (int mt = 0; mt < 4; mt++) {
#pragma unroll
        for (int h = 0; h < 2; h++) {
            float b = bv[mt][h], s = sv[mt][h];
            int   i = bi[mt][h];
#pragma unroll
            for (int m = 1; m <= 2; m <<= 1) {
                float b2 = __shfl_xor_sync(0xffffffffu, b, m);
                float s2 = __shfl_xor_sync(0xffffffffu, s, m);
                int   i2 = __shfl_xor_sync(0xffffffffu, i, m);
                if (b2 < b || (b2 == b && i2 < i)) { s = fminf(b, s2); b = b2; i = i2; }
                else s = fminf(s, b2);
            }
            if (tq == 0) {
                const int rl = wm * 64 + mt * 16 + gq + 8 * h;
                RV[rl * 4 + wn] = b; RS[rl * 4 + wn] = s; RI[rl * 4 + wn] = i;
            }
        }
    }
    __syncthreads();
    if (tid < 128 && base + tid < nf) {
        float b = RV[tid * 4], s = RS[tid * 4];
        int   i = RI[tid * 4];
#pragma unroll
        for (int w = 1; w < 4; w++) {
            float b2 = RV[tid * 4 + w], s2 = RS[tid * 4 + w];
            int   i2 = RI[tid * 4 + w];
            if (b2 < b || (b2 == b && i2 < i)) { s = fminf(b, s2); b = b2; i = i2; }
            else s = fminf(s, b2);
        }
        const int f = base + tid;
        g_l2v[f * L2_PARTS + part] = b;
        g_l2s[f * L2_PARTS + part] = s;
        g_l2i[f * L2_PARTS + part] = i;
    }
}

__global__ void l2_combine() {
    int f = blockIdx.x * 256 + threadIdx.x;
    const int nf = g_flagcnt;
    if (f >= nf) return;
    float b = g_l2v[f * L2_PARTS], s = g_l2s[f * L2_PARTS];
    int   i = g_l2i[f * L2_PARTS];
#pragma unroll
    for (int w = 1; w < L2_PARTS; w++) {
        float b2 = g_l2v[f * L2_PARTS + w], s2 = g_l2s[f * L2_PARTS + w];
        int   i2 = g_l2i[f * L2_PARTS + w];
        if (b2 < b || (b2 == b && i2 < i)) { s = fminf(b, s2); b = b2; i = i2; }
        else s = fminf(s, b2);
    }
    const int row = g_flagrows[f];
    g_idx[row] = i;
    if (s - b < EPS_SCALED) {
        int p = atomicAdd(&g_flagcnt2, 1);
        g_flagrows2[p] = row;
    }
}

// ---------------- Level-3 exact fp32 recheck ----------------
__global__ void __launch_bounds__(256)
recheck_k(const float* __restrict__ cb) {
    __shared__ float lrow[32][cD + 4];
    __shared__ float crow[8][cD + 4];
    __shared__ int   rowid[32];
    __shared__ float rnv[32];
    const int tid = threadIdx.x;
    const int nf = g_flagcnt2;
    const int ntiles = (nf + 31) >> 5;
    const int r = tid >> 3;
    const int cl = tid & 7;

    for (int tile = blockIdx.x; tile < ntiles; tile += gridDim.x) {
        __syncthreads();
        if (tid < 32) {
            int f = tile * 32 + tid;
            int row = (f < nf) ? g_flagrows2[f] : -1;
            rowid[tid] = row;
            rnv[tid] = (row >= 0) ? g_rn[row] : 0.0f;
        }
        __syncthreads();
        for (int i = tid; i < 32 * 32; i += 256) {
            int rr = i >> 5, seg = i & 31;
            int row = rowid[rr];
            float4 v = (row >= 0)
                ? reinterpret_cast<const float4*>(g_lat + (size_t)row * cD)[seg]
                : make_float4(0.f, 0.f, 0.f, 0.f);
            *reinterpret_cast<float4*>(&lrow[rr][seg * 4]) = v;
        }
        __syncthreads();

        float bvv = INFINITY; int bii = 0;
        const float rn = rnv[r];
        for (int k0 = 0; k0 < cK; k0 += 8) {
            {
                int cr = tid >> 5, seg = tid & 31;
                *reinterpret_cast<float4*>(&crow[cr][seg * 4]) =
                    reinterpret_cast<const float4*>(cb + (size_t)(k0 + cr) * cD)[seg];
            }
            __syncthreads();
            float dot = 0.0f;
#pragma unroll
            for (int d4 = 0; d4 < 32; d4++) {
                float4 a = *reinterpret_cast<const float4*>(&lrow[r][d4 * 4]);
                float4 b = *reinterpret_cast<const float4*>(&crow[cl][d4 * 4]);
                dot = fmaf(a.x, b.x, dot); dot = fmaf(a.y, b.y, dot);
                dot = fmaf(a.z, b.z, dot); dot = fmaf(a.w, b.w, dot);
            }
            const int k = k0 + cl;
            float s1 = __fadd_rn(rn, g_cn[k]);
            float dd = __fadd_rn(s1, -2.0f * dot);
            if (dd < bvv) { bvv = dd; bii = k; }
            __syncthreads();
        }
#pragma unroll
        for (int m = 1; m <= 4; m <<= 1) {
            float b2 = __shfl_xor_sync(0xffffffffu, bvv, m);
            int   i2 = __shfl_xor_sync(0xffffffffu, bii, m);
            if (b2 < bvv || (b2 == bvv && i2 < bii)) { bvv = b2; bii = i2; }
        }
        if (cl == 0 && rowid[r] >= 0) g_idx[rowid[r]] = bii;
    }
}

// gather: 64 rows/block, one atomic per block
__global__ void __launch_bounds__(256)
gather_vq(const float* __restrict__ cb, float* __restrict__ outIdxF) {
    __shared__ float wsum[8];
    const int tid = threadIdx.x;
    const int warp = tid >> 5, lane = tid & 31;
    float s = 0.0f;
#pragma unroll
    for (int it = 0; it < 8; it++) {
        const int row = blockIdx.x * 64 + warp * 8 + it;
        const int id = g_idx[row];
        float4 c = reinterpret_cast<const float4*>(cb)[(size_t)id * 32 + lane];
        float4 l = reinterpret_cast<const float4*>(g_lat)[(size_t)row * 32 + lane];
        if (lane < 16) {
            reinterpret_cast<uint4*>(g_qH + (size_t)row * cD)[lane] =
                reinterpret_cast<const uint4*>(g_cbH + (size_t)id * cD)[lane];
        } else {
            reinterpret_cast<uint4*>(g_qL + (size_t)row * cD)[lane - 16] =
                reinterpret_cast<const uint4*>(g_cbL + (size_t)id * cD)[lane - 16];
        }
        float dx = c.x - l.x, dy = c.y - l.y, dz = c.z - l.z, dw = c.w - l.w;
        s += dx * dx + dy * dy + dz * dz + dw * dw;
        if (lane == 0 && outIdxF) outIdxF[row] = (float)id;
    }
#pragma unroll
    for (int off = 16; off > 0; off >>= 1) s += __shfl_down_sync(0xffffffffu, s, off);
    if (lane == 0) wsum[warp] = s;
    __syncthreads();
    if (tid == 0) {
        float t = 0.0f;
#pragma unroll
        for (int w = 0; w < 8; w++) t += wsum[w];
        atomicAdd(&g_vq_sum, t);
    }
}

__global__ void finalize_k(float* __restrict__ out, int out_size) {
    if (out_size >= FULL_OUT) {
        float m = g_vq_sum / (float)(cB * cN * cD);
        float vq = 1.25f * m;
        float rl = g_recon_sum / (float)RECON_ELEMS;
        out[SCALAR_OFF + 0] = vq;
        out[SCALAR_OFF + 1] = rl;
        out[SCALAR_OFF + 2] = rl + vq;
    }
}

// ---------------- launch ----------------
extern "C" void kernel_launch(void* const* d_in, const int* in_sizes, int n_in,
                              void* d_out, int out_size) {
    const float* actions = (const float*)d_in[0];
    const float* e_w1 = (const float*)d_in[1];
    const float* e_b1 = (const float*)d_in[2];
    const float* e_w2 = (const float*)d_in[3];
    const float* e_b2 = (const float*)d_in[4];
    const float* e_w3 = (const float*)d_in[5];
    const float* e_b3 = (const float*)d_in[6];
    const float* cb   = (const float*)d_in[7];
    const float* d_w1 = (const float*)d_in[8];
    const float* d_b1 = (const float*)d_in[9];
    const float* d_w2 = (const float*)d_in[10];
    const float* d_b2 = (const float*)d_in[11];
    const float* d_w3 = (const float*)d_in[12];
    const float* d_b3 = (const float*)d_in[13];
    float* out = (float*)d_out;

    float *p_h1, *p_h2, *p_lat;
    cudaGetSymbolAddress((void**)&p_h1,  g_h1);
    cudaGetSymbolAddress((void**)&p_h2,  g_h2);
    cudaGetSymbolAddress((void**)&p_lat, g_lat);
    __half *latH, *latL, *qH, *qL, *g1H, *g1L, *g2H, *g2L, *cbH, *cbL;
    __half *v1H, *v1L, *v2H, *v2L, *v3H, *v3L;
    cudaGetSymbolAddress((void**)&latH, g_latH); cudaGetSymbolAddress((void**)&latL, g_latL);
    cudaGetSymbolAddress((void**)&qH, g_qH);     cudaGetSymbolAddress((void**)&qL, g_qL);
    cudaGetSymbolAddress((void**)&g1H, g_g1H);   cudaGetSymbolAddress((void**)&g1L, g_g1L);
    cudaGetSymbolAddress((void**)&g2H, g_g2H);   cudaGetSymbolAddress((void**)&g2L, g_g2L);
    cudaGetSymbolAddress((void**)&cbH, g_cbH);   cudaGetSymbolAddress((void**)&cbL, g_cbL);
    cudaGetSymbolAddress((void**)&v1H, g_v1H);   cudaGetSymbolAddress((void**)&v1L, g_v1L);
    cudaGetSymbolAddress((void**)&v2H, g_v2H);   cudaGetSymbolAddress((void**)&v2L, g_v2L);
    cudaGetSymbolAddress((void**)&v3H, g_v3H);   cudaGetSymbolAddress((void**)&v3L, g_v3L);

    static cudaStream_t s2 = nullptr;
    static cudaEvent_t evFork = nullptr, evA = nullptr, evC = nullptr;
    static bool attr_done = false;
    if (!attr_done) {
        cudaFuncSetAttribute(argmin_l1, cudaFuncAttributeMaxDynamicSharedMemorySize, ARG_SMEM1);
        cudaFuncSetAttribute(argmin_l2, cudaFuncAttributeMaxDynamicSharedMemorySize, ARG_SMEM2);
        cudaFuncSetAttribute((const void*)mma_gemm<1, 1>, cudaFuncAttributeMaxDynamicSharedMemorySize, DEC_SMEM);
        cudaFuncSetAttribute((const void*)mma_gemm<2, 3>, cudaFuncAttributeMaxDynamicSharedMemorySize, DEC_SMEM);
        cudaStreamCreateWithFlags(&s2, cudaStreamNonBlocking);
        cudaEventCreateWithFlags(&evFork, cudaEventDisableTiming);
        cudaEventCreateWithFlags(&evA, cudaEventDisableTiming);
        cudaEventCreateWithFlags(&evC, cudaEventDisableTiming);
        attr_done = true;
    }

    const bool has_idx = out_size >= (IDX_OFF + cROWS);
    dim3 wt(32, 8);

    // fork: prep chain on s2 (independent of encoder)
    cudaEventRecord(evFork, 0);
    cudaStreamWaitEvent(s2, evFork, 0);
    cn_kernel<<<cK / 8, 256, 0, s2>>>(cb);
    cnmax_kernel<<<1, 256, 0, s2>>>();
    split_act<<<(cK * cD / 4 + 255) / 256, 256, 0, s2>>>(cb, cbH, cbL, cK * cD / 4);
    wsplit<<<dim3(cHID / 32, cLAT / 32), wt, 0, s2>>>(d_w1, v1H, v1L, cLAT, cHID);
    wsplit<<<dim3(cHID / 32, cHID / 32), wt, 0, s2>>>(d_w2, v2H, v2L, cHID, cHID);
    wsplit<<<dim3(cFLAT / 32 + 1, cHID / 32), wt, 0, s2>>>(d_w3, v3H, v3L, cHID, cFLAT);

    // main: encoder (fp32, bit-identical arithmetic); enc3 split into halves
    init_accum<<<1, 1>>>();
    sgemm_k<1, false><<<dim3(cHID / BN, cB / BM), 256>>>(actions, e_w1, e_b1, p_h1, cB, cHID, cFLAT, nullptr, nullptr, 0);
    sgemm_k<1, false><<<dim3(cHID / BN, cB / BM), 256>>>(p_h1, e_w2, e_b2, p_h2, cB, cHID, cHID, nullptr, nullptr, 0);
    sgemm_k<0, true><<<dim3(cLAT / BN, cB / BM / 2), 256>>>(p_h2, e_w3, e_b3, p_lat, cB, cLAT, cHID, latH, latL, 0);
    cudaEventRecord(evA, 0);

    // s2: first-half argmin L1 overlapped with second-half enc3
    cudaStreamWaitEvent(s2, evA, 0);
    rn_kernel<<<cROWS / 16, 256, 0, s2>>>(0);
    argmin_l1<<<cROWS / 256, 256, ARG_SMEM1, s2>>>(0);
    cudaEventRecord(evC, s2);

    // main: second half enc3 + its argmin
    sgemm_k<0, true><<<dim3(cLAT / BN, cB / BM / 2), 256>>>(p_h2, e_w3, e_b3, p_lat, cB, cLAT, cHID, latH, latL, cB / BM / 2);
    rn_kernel<<<cROWS / 16, 256>>>(cROWS / 2);
    argmin_l1<<<cROWS / 256, 256, ARG_SMEM1>>>(cROWS / 256);
    cudaStreamWaitEvent(0, evC, 0);

    // quantization — hierarchical argmin tail
    argmin_l2<<<dim3(cROWS / 128, L2_PARTS), 256, ARG_SMEM2>>>();
    l2_combine<<<cROWS / 256, 256>>>();
    recheck_k<<<148, 256>>>(cb);
    gather_vq<<<cROWS / 64, 256>>>(cb, has_idx ? (out + IDX_OFF) : nullptr);

    // decoder — d1/d2 1-pass (hh) split-fp16 HMMA, d3 full 3-pass
    mma_gemm<1, 1><<<dim3(cHID / 128, cB / 128), 256, DEC_SMEM>>>(qH, qL, v1H, v1L, d_b1, nullptr, g1H, g1L, cB, cHID, cLAT, nullptr);
    mma_gemm<1, 1><<<dim3(cHID / 128, cB / 128), 256, DEC_SMEM>>>(g1H, g1L, v2H, v2L, d_b2, nullptr, g2H, g2L, cB, cHID, cHID, nullptr);
    mma_gemm<2, 3><<<dim3(1, cB / 128), 256, DEC_SMEM>>>(g2H, g2L, v3H, v3L, d_b3, out, nullptr, nullptr, cB, cFLAT, cHID, actions);

    finalize_k<<<1, 1>>>(out, out_size);
}

// round 17
// speedup vs baseline: 1.0582x; 1.0327x over previous
#include <cuda_runtime.h>
#include <cuda_fp16.h>
#include <math.h>
#include <stdint.h>

#define BM 128
#define BN 128
#define BKd 8
#define TM 8
#define TN 8

static constexpr int cB    = 4096;
static constexpr int cT    = 32;
static constexpr int cA    = 3;
static constexpr int cFLAT = 96;
static constexpr int cHID  = 1024;
static constexpr int cD    = 128;
static constexpr int cN    = 16;
static constexpr int cK    = 4096;
static constexpr int cLAT  = 2048;
static constexpr int cROWS = cB * cN;               // 65536
static constexpr int RECON_ELEMS = cB * cT * cA;    // 393216
static constexpr int IDX_OFF     = RECON_ELEMS;
static constexpr int SCALAR_OFF  = IDX_OFF + cROWS;
static constexpr int FULL_OUT    = SCALAR_OFF + 3;

static constexpr float SSCALE   = 256.0f;
static constexpr float LOSCALE  = 2048.0f;
static constexpr float INV_LO   = 4.8828125e-4f;     // 2^-11
static constexpr float INV_FULL = 1.52587890625e-5f; // 2^-16
static constexpr float EPS_SCALED = 2e-7f * 65536.0f;

static constexpr int L2_PARTS = 4;
static constexpr int L2_TILES_PER_PART = (cK / 128) / L2_PARTS;  // 8

// ---------------- scratch ----------------
__device__ float g_h1 [cB * cHID];
__device__ float g_h2 [cB * cHID];
__device__ float g_lat[cB * cLAT];
__device__ float g_cn [cK];
__device__ float g_rn [cROWS];
__device__ int   g_idx[cROWS];
__device__ float g_vq_sum;
__device__ float g_recon_sum;
__device__ int   g_flagcnt;
__device__ int   g_flagrows[cROWS];
__device__ int   g_flagcnt2;
__device__ int   g_flagrows2[cROWS];
__device__ float g_cnmax;
__device__ float g_l2v[cROWS * L2_PARTS];
__device__ float g_l2s[cROWS * L2_PARTS];
__device__ int   g_l2i[cROWS * L2_PARTS];

__device__ __half g_latH[cROWS * cD], g_latL[cROWS * cD];
__device__ __half g_qH [cB * cLAT],   g_qL [cB * cLAT];
__device__ __half g_g1H[cB * cHID],   g_g1L[cB * cHID];
__device__ __half g_g2H[cB * cHID],   g_g2L[cB * cHID];
__device__ __half g_cbH[cK * cD],     g_cbL[cK * cD];
__device__ __half g_v1H[cHID * cLAT],  g_v1L[cHID * cLAT];
__device__ __half g_v2H[cHID * cHID],  g_v2L[cHID * cHID];
__device__ __half g_v3H[cFLAT * cHID], g_v3L[cFLAT * cHID];

// ---------------- low-level helpers ----------------
typedef unsigned long long u64;
__device__ __forceinline__ u64 pack2(float lo, float hi) {
    u64 r;
    asm("mov.b64 %0, {%1, %2};" : "=l"(r) : "r"(__float_as_uint(lo)), "r"(__float_as_uint(hi)));
    return r;
}
__device__ __forceinline__ void fma2(u64 &d, u64 a, u64 b) {
    asm("fma.rn.f32x2 %0, %1, %2, %0;" : "+l"(d) : "l"(a), "l"(b));
}
__device__ __forceinline__ void unpack2(u64 v, float &lo, float &hi) {
    unsigned int l, h;
    asm("mov.b64 {%0, %1}, %2;" : "=r"(l), "=r"(h) : "l"(v));
    lo = __uint_as_float(l); hi = __uint_as_float(h);
}

__device__ __forceinline__ float silu_f(float x) {
    float s;
    if (x >= 0.0f) s = 1.0f / (1.0f + expf(-x));
    else { float e = expf(x); s = e / (1.0f + e); }
    return x * s;
}

__device__ __forceinline__ void mma16816(float c[4], uint32_t a0, uint32_t a1,
                                         uint32_t a2, uint32_t a3,
                                         uint32_t b0, uint32_t b1) {
    asm volatile(
        "mma.sync.aligned.m16n8k16.row.col.f32.f16.f16.f32 "
        "{%0,%1,%2,%3},{%4,%5,%6,%7},{%8,%9},{%0,%1,%2,%3};"
        : "+f"(c[0]), "+f"(c[1]), "+f"(c[2]), "+f"(c[3])
        : "r"(a0), "r"(a1), "r"(a2), "r"(a3), "r"(b0), "r"(b1));
}

__device__ __forceinline__ void ldsm4(uint32_t r[4], uint32_t addr) {
    asm volatile("ldmatrix.sync.aligned.m8n8.x4.shared.b16 {%0,%1,%2,%3}, [%4];"
                 : "=r"(r[0]), "=r"(r[1]), "=r"(r[2]), "=r"(r[3]) : "r"(addr));
}

__device__ __forceinline__ void cp_async16(void* dst, const void* src) {
    uint32_t d = (uint32_t)__cvta_generic_to_shared(dst);
    asm volatile("cp.async.cg.shared.global [%0], [%1], 16;" :: "r"(d), "l"(src));
}
#define CP_COMMIT() asm volatile("cp.async.commit_group;" ::: "memory")
#define CP_WAIT2()  asm volatile("cp.async.wait_group 2;" ::: "memory")

__global__ void init_accum() {
    g_vq_sum = 0.0f; g_recon_sum = 0.0f; g_flagcnt = 0; g_flagcnt2 = 0;
}

__global__ void cn_kernel(const float* __restrict__ cb) {
    int warp = (blockIdx.x * blockDim.x + threadIdx.x) >> 5;
    int lane = threadIdx.x & 31;
    if (warp >= cK) return;
    const float4 v = reinterpret_cast<const float4*>(cb)[warp * 32 + lane];
    double a = (double)v.x * v.x + (double)v.y * v.y + (double)v.z * v.z + (double)v.w * v.w;
#pragma unroll
    for (int off = 16; off > 0; off >>= 1) a += __shfl_down_sync(0xffffffffu, a, off);
    if (lane == 0) g_cn[warp] = (float)a;
}

__global__ void cnmax_kernel() {
    __shared__ float red[256];
    float m = 0.0f;
    for (int i = threadIdx.x; i < cK; i += 256) m = fmaxf(m, g_cn[i]);
    red[threadIdx.x] = m;
    __syncthreads();
    for (int s = 128; s > 0; s >>= 1) {
        if (threadIdx.x < s) red[threadIdx.x] = fmaxf(red[threadIdx.x], red[threadIdx.x + s]);
        __syncthreads();
    }
    if (threadIdx.x == 0) g_cnmax = sqrtf(red[0]);
}

__global__ void rn_kernel(int rowoff) {
    int warp = rowoff + ((blockIdx.x * blockDim.x + threadIdx.x) >> 5);
    int lane = threadIdx.x & 31;
    if (warp >= cROWS) return;
    const float4 v = reinterpret_cast<const float4*>(g_lat)[(size_t)warp * 32 + lane];
    double a = (double)v.x * v.x + (double)v.y * v.y + (double)v.z * v.z + (double)v.w * v.w;
#pragma unroll
    for (int off = 16; off > 0; off >>= 1) a += __shfl_down_sync(0xffffffffu, a, off);
    if (lane == 0) g_rn[warp] = (float)a;
}

__global__ void split_act(const float* __restrict__ src, __half* __restrict__ hi,
                          __half* __restrict__ lo, int n4) {
    int i = blockIdx.x * blockDim.x + threadIdx.x;
    if (i >= n4) return;
    float4 v = reinterpret_cast<const float4*>(src)[i];
    float x0 = v.x * SSCALE, x1 = v.y * SSCALE, x2 = v.z * SSCALE, x3 = v.w * SSCALE;
    __half h0 = __float2half_rn(x0), h1 = __float2half_rn(x1);
    __half h2 = __float2half_rn(x2), h3 = __float2half_rn(x3);
    __half2* hp = reinterpret_cast<__half2*>(hi);
    hp[i * 2 + 0] = __half2(h0, h1);
    hp[i * 2 + 1] = __half2(h2, h3);
    __half2* lp = reinterpret_cast<__half2*>(lo);
    lp[i * 2 + 0] = __half2(__float2half_rn((x0 - __half2float(h0)) * LOSCALE),
                            __float2half_rn((x1 - __half2float(h1)) * LOSCALE));
    lp[i * 2 + 1] = __half2(__float2half_rn((x2 - __half2float(h2)) * LOSCALE),
                            __float2half_rn((x3 - __half2float(h3)) * LOSCALE));
}

__global__ void wsplit(const float* __restrict__ W, __half* __restrict__ WtH,
                       __half* __restrict__ WtL, int Kd, int N) {
    __shared__ float tile[32][33];
    const int bx = blockIdx.x * 32, by = blockIdx.y * 32;
    const int tx = threadIdx.x, ty = threadIdx.y;
    for (int r = ty; r < 32; r += 8) {
        int n = bx + tx;
        tile[r][tx] = (n < N) ? W[(size_t)(by + r) * N + n] : 0.0f;
    }
    __syncthreads();
    for (int r = ty; r < 32; r += 8) {
        int n = bx + r, k = by + tx;
        if (n < N) {
            float x = tile[tx][r] * SSCALE;
            __half h = __float2half_rn(x);
            WtH[(size_t)n * Kd + k] = h;
            WtL[(size_t)n * Kd + k] = __float2half_rn((x - __half2float(h)) * LOSCALE);
        }
    }
}

// ---------------- fp32 SGEMM (f32x2) — encoder (bit-identical path) ----------------
template <int MODE, bool SPLITOUT>
__global__ void __launch_bounds__(256)
sgemm_k(const float* __restrict__ Ag, const float* __restrict__ Bg,
        const float* __restrict__ bias, float* __restrict__ Cg,
        int M, int N, int Kd, __half* __restrict__ hiP, __half* __restrict__ loP,
        int yoff) {
    __shared__ float As[2][BKd][BM];
    __shared__ float Bs[2][BKd][BN];
    const int tid = threadIdx.x;
    const int rbase = (blockIdx.y + yoff) * BM, cbase = blockIdx.x * BN;
    const int rowA = tid >> 1, colA4 = (tid & 1) * 4;
    const int rowB = tid >> 5, colB4 = (tid & 31) * 4;
    const int tr = (tid >> 4) * TM, tc = (tid & 15) * TN;

    u64 acc[TM][TN / 2];
#pragma unroll
    for (int i = 0; i < TM; i++)
#pragma unroll
        for (int j = 0; j < TN / 2; j++) acc[i][j] = 0ull;

    const int nt = Kd / BKd;
    const bool bok = (cbase + colB4 < N);

    {
        float4 pa = *reinterpret_cast<const float4*>(&Ag[(size_t)(rbase + rowA) * Kd + colA4]);
        float4 pb = make_float4(0.f, 0.f, 0.f, 0.f);
        if (bok) pb = *reinterpret_cast<const float4*>(&Bg[(size_t)rowB * N + cbase + colB4]);
        As[0][colA4 + 0][rowA] = pa.x; As[0][colA4 + 1][rowA] = pa.y;
        As[0][colA4 + 2][rowA] = pa.z; As[0][colA4 + 3][rowA] = pa.w;
        *reinterpret_cast<float4*>(&Bs[0][rowB][colB4]) = pb;
    }

    for (int t = 0; t < nt; t++) {
        const int cur = t & 1;
        float4 pa, pb;
        const bool more = (t + 1 < nt);
        if (more) {
            pa = *reinterpret_cast<const float4*>(
                &Ag[(size_t)(rbase + rowA) * Kd + (t + 1) * BKd + colA4]);
            pb = make_float4(0.f, 0.f, 0.f, 0.f);
            if (bok)
                pb = *reinterpret_cast<const float4*>(
                    &Bg[(size_t)((t + 1) * BKd + rowB) * N + cbase + colB4]);
        }
        __syncthreads();
#pragma unroll
        for (int k = 0; k < BKd; k++) {
            float4 a0 = *reinterpret_cast<const float4*>(&As[cur][k][tr]);
            float4 a1 = *reinterpret_cast<const float4*>(&As[cur][k][tr + 4]);
            const u64* bp = reinterpret_cast<const u64*>(&Bs[cur][k][tc]);
            u64 b0 = bp[0], b1 = bp[1], b2 = bp[2], b3 = bp[3];
            float am[TM] = {a0.x, a0.y, a0.z, a0.w, a1.x, a1.y, a1.z, a1.w};
#pragma unroll
            for (int i = 0; i < TM; i++) {
                u64 ap = pack2(am[i], am[i]);
                fma2(acc[i][0], ap, b0); fma2(acc[i][1], ap, b1);
                fma2(acc[i][2], ap, b2); fma2(acc[i][3], ap, b3);
            }
        }
        if (more) {
            const int nxt = cur ^ 1;
            As[nxt][colA4 + 0][rowA] = pa.x; As[nxt][colA4 + 1][rowA] = pa.y;
            As[nxt][colA4 + 2][rowA] = pa.z; As[nxt][colA4 + 3][rowA] = pa.w;
            *reinterpret_cast<float4*>(&Bs[nxt][rowB][colB4]) = pb;
        }
    }

#pragma unroll
    for (int i = 0; i < TM; i++) {
        const int row = rbase + tr + i;
#pragma unroll
        for (int j = 0; j < TN / 2; j++) {
            const int c0 = cbase + tc + 2 * j;
            if (c0 < N) {
                float lo, hi; unpack2(acc[i][j], lo, hi);
                float v0 = lo + bias[c0], v1 = hi + bias[c0 + 1];
                if (MODE == 1) { v0 = silu_f(v0); v1 = silu_f(v1); }
                Cg[(size_t)row * N + c0]     = v0;
                Cg[(size_t)row * N + c0 + 1] = v1;
                if (SPLITOUT) {
                    float x0 = v0 * SSCALE, x1 = v1 * SSCALE;
                    __half h0 = __float2half_rn(x0), h1 = __float2half_rn(x1);
                    *reinterpret_cast<__half2*>(&hiP[(size_t)row * N + c0]) = __half2(h0, h1);
                    *reinterpret_cast<__half2*>(&loP[(size_t)row * N + c0]) =
                        __half2(__float2half_rn((x0 - __half2float(h0)) * LOSCALE),
                                __float2half_rn((x1 - __half2float(h1)) * LOSCALE));
                }
            }
        }
    }
}

// ---------------- split-fp16 HMMA GEMM — decoder ----------------
static constexpr int KP   = 40;
static constexpr int STG  = 128 * KP;
static constexpr int DEC_SMEM = 4 * 2 * STG * 2;  // 81920 bytes

template <int MODE, int PASSES>
__global__ void __launch_bounds__(256)
mma_gemm(const __half* __restrict__ Ah, const __half* __restrict__ Al,
         const __half* __restrict__ Bh, const __half* __restrict__ Bl,
         const float* __restrict__ bias, float* __restrict__ Cg,
         __half* __restrict__ hiP, __half* __restrict__ loP,
         int M, int N, int Kd, const float* __restrict__ ref) {
    extern __shared__ __align__(16) __half dsm[];
    __half* As = dsm;
    __half* Bs = dsm + 4 * STG;

    const int tid = threadIdx.x;
    const int lane = tid & 31, warp = tid >> 5;
    const int wm = warp >> 2, wn = warp & 3;
    const int gq = lane >> 2, tq = lane & 3;
    const int rbase = blockIdx.y * 128, cbase = blockIdx.x * 128;

    const int KC = Kd >> 5;
    const int NCH = PASSES * KC;
    const int RESC = (PASSES > 1) ? (PASSES - 1) * KC : -1;

    if (N < 128) {
        const uint4 z4 = make_uint4(0, 0, 0, 0);
        for (int i = tid; i < 4 * STG / 8; i += 256)
            *reinterpret_cast<uint4*>(Bs + i * 8) = z4;
    }

    float acc[4][4][4];
#pragma unroll
    for (int a = 0; a < 4; a++)
#pragma unroll
        for (int b = 0; b < 4; b++)
#pragma unroll
            for (int c = 0; c < 4; c++) acc[a][b][c] = 0.0f;

    auto loadAB = [&](int c, int st) {
        const int p = c / KC, kc = c % KC;
        const __half* Asrc = (PASSES == 3 && p == 1) ? Al : Ah;
        const __half* Bsrc = (PASSES > 1 && p == 0) ? Bl : Bh;
#pragma unroll
        for (int j = 0; j < 2; j++) {
            int i = tid + 256 * j;
            int row = i >> 2, seg = i & 3;
            cp_async16(As + st * STG + row * KP + seg * 8,
                       Asrc + (size_t)(rbase + row) * Kd + kc * 32 + seg * 8);
            int col = cbase + row;
            if (col < N)
                cp_async16(Bs + st * STG + row * KP + seg * 8,
                           Bsrc + (size_t)col * Kd + kc * 32 + seg * 8);
        }
    };

    const uint32_t aRow = (lane & 7) + ((lane >> 3) & 1) * 8;
    const uint32_t aK   = (lane >> 4) * 8;
    const uint32_t bRow = ((lane >> 4) & 1) * 8 + (lane & 7);
    const uint32_t bK   = ((lane >> 3) & 1) * 8;
    const uint32_t aBase0 = (uint32_t)__cvta_generic_to_shared(As) +
                            ((wm * 64 + aRow) * KP + aK) * 2;
    const uint32_t bBase0 = (uint32_t)__cvta_generic_to_shared(Bs) +
                            ((wn * 32 + bRow) * KP + bK) * 2;

    loadAB(0, 0); CP_COMMIT();
    loadAB(1, 1); CP_COMMIT();
    for (int c = 0; c < NCH; c++) {
        if (c + 2 < NCH) loadAB(c + 2, (c + 2) & 3);
        CP_COMMIT();
        CP_WAIT2();
        __syncthreads();
        if (PASSES > 1 && c == RESC) {
#pragma unroll
            for (int a = 0; a < 4; a++)
#pragma unroll
                for (int b = 0; b < 4; b++)
#pragma unroll
                    for (int q = 0; q < 4; q++) acc[a][b][q] *= INV_LO;
        }
        const uint32_t aSt = aBase0 + ((c & 3) * STG) * 2;
        const uint32_t bSt = bBase0 + ((c & 3) * STG) * 2;
#pragma unroll
        for (int ks = 0; ks < 2; ks++) {
            const int k0 = ks * 16;
            uint32_t af[4][4];
#pragma unroll
            for (int mt = 0; mt < 4; mt++)
                ldsm4(af[mt], aSt + (mt * 16 * KP + k0) * 2);
            uint32_t bf[2][4];
#pragma unroll
            for (int pr = 0; pr < 2; pr++)
                ldsm4(bf[pr], bSt + (pr * 16 * KP + k0) * 2);
#pragma unroll
            for (int nt = 0; nt < 4; nt++) {
                uint32_t b0 = bf[nt >> 1][(nt & 1) * 2 + 0];
                uint32_t b1 = bf[nt >> 1][(nt & 1) * 2 + 1];
#pragma unroll
                for (int mt = 0; mt < 4; mt++)
                    mma16816(acc[mt][nt], af[mt][0], af[mt][1], af[mt][2], af[mt][3], b0, b1);
            }
        }
    }

    float lsum = 0.0f;
#pragma unroll
    for (int mt = 0; mt < 4; mt++) {
#pragma unroll
        for (int nt = 0; nt < 4; nt++) {
            const int row0 = rbase + wm * 64 + mt * 16 + gq;
            const int col0 = cbase + wn * 32 + nt * 8 + tq * 2;
            if (col0 < N) {
                const float bz0 = bias[col0], bz1 = bias[col0 + 1];
#pragma unroll
                for (int h = 0; h < 2; h++) {
                    const int row = row0 + 8 * h;
                    float v0 = acc[mt][nt][2 * h + 0] * INV_FULL + bz0;
                    float v1 = acc[mt][nt][2 * h + 1] * INV_FULL + bz1;
                    if (MODE == 1) {
                        v0 = silu_f(v0); v1 = silu_f(v1);
                        float x0 = v0 * SSCALE, x1 = v1 * SSCALE;
                        __half h0 = __float2half_rn(x0), h1 = __float2half_rn(x1);
                        *reinterpret_cast<__half2*>(&hiP[(size_t)row * N + col0]) = __half2(h0, h1);
                        *reinterpret_cast<__half2*>(&loP[(size_t)row * N + col0]) =
                            __half2(__float2half_rn((x0 - __half2float(h0)) * LOSCALE),
                                    __float2half_rn((x1 - __half2float(h1)) * LOSCALE));
                    } else {
                        Cg[(size_t)row * N + col0]     = v0;
                        Cg[(size_t)row * N + col0 + 1] = v1;
                        float d0 = v0 - ref[(size_t)row * N + col0];
                        float d1 = v1 - ref[(size_t)row * N + col0 + 1];
                        lsum = fmaf(d0, d0, fmaf(d1, d1, lsum));
                    }
                }
            }
        }
    }
    if (MODE == 2) {
        __shared__ float red[256];
        red[tid] = lsum; __syncthreads();
        for (int s = 128; s > 0; s >>= 1) { if (tid < s) red[tid] += red[tid + s]; __syncthreads(); }
        if (tid == 0) atomicAdd(&g_recon_sum, red[0]);
    }
}

// ---------------- Level-1 HMMA argmin — hi-only + sound flag ----------------
static constexpr int KPA = 136;
static constexpr int KPB = 40;
static constexpr int B_STGH = 128 * KPB;
static constexpr int ARG_SMEM1 =
    (128 * KPA + 4 * B_STGH) * 2 + (cK + 512 * 3) * 4;   // 98304

__global__ void __launch_bounds__(256)
argmin_l1(int boff) {
    extern __shared__ __align__(16) __half dsm[];
    __half* a_h = dsm;
    __half* bs  = dsm + 128 * KPA;
    float*  cn_s = reinterpret_cast<float*>(dsm + 128 * KPA + 4 * B_STGH);
    float*  RV = cn_s + cK;
    float*  RS = RV + 512;
    int*    RI = reinterpret_cast<int*>(RS + 512);

    const int tid = threadIdx.x;
    const int lane = tid & 31, warp = tid >> 5;
    const int wm = warp >> 2, wn = warp & 3;
    const int gq = lane >> 2, tq = lane & 3;
    const int rbase = (blockIdx.x + boff) * 128;

#pragma unroll
    for (int j = 0; j < 8; j++) {
        int i = tid + 256 * j;
        int row = i >> 4, seg = i & 15;
        *reinterpret_cast<uint4*>(a_h + row * KPA + seg * 8) =
            *reinterpret_cast<const uint4*>(g_latH + (size_t)(rbase + row) * cD + seg * 8);
    }
    for (int i = tid; i < cK / 4; i += 256) {
        float4 v = reinterpret_cast<const float4*>(g_cn)[i];
        v.x *= 65536.0f; v.y *= 65536.0f; v.z *= 65536.0f; v.w *= 65536.0f;
        reinterpret_cast<float4*>(cn_s)[i] = v;
    }

    float rnr[4][2];
#pragma unroll
    for (int mt = 0; mt < 4; mt++)
#pragma unroll
        for (int h = 0; h < 2; h++)
            rnr[mt][h] = g_rn[rbase + wm * 64 + mt * 16 + gq + 8 * h] * 65536.0f;

    float bv[4][2], sv[4][2];
    int   bi[4][2];
#pragma unroll
    for (int mt = 0; mt < 4; mt++)
#pragma unroll
        for (int h = 0; h < 2; h++) { bv[mt][h] = INFINITY; sv[mt][h] = INFINITY; bi[mt][h] = 0; }

    float acc[4][4][4];
#pragma unroll
    for (int a = 0; a < 4; a++)
#pragma unroll
        for (int b = 0; b < 4; b++)
#pragma unroll
            for (int q = 0; q < 4; q++) acc[a][b][q] = 0.0f;

    auto loadB = [&](int c, int st) {
        const int ct = c >> 2, kc = c & 3;
#pragma unroll
        for (int j = 0; j < 2; j++) {
            int i = tid + 256 * j;
            int row = i >> 2, seg = i & 3;
            cp_async16(bs + st * B_STGH + row * KPB + seg * 8,
                       g_cbH + (size_t)(ct * 128 + row) * cD + kc * 32 + seg * 8);
        }
    };

    const uint32_t aRow = (lane & 7) + ((lane >> 3) & 1) * 8;
    const uint32_t aK   = (lane >> 4) * 8;
    const uint32_t bRow = ((lane >> 4) & 1) * 8 + (lane & 7);
    const uint32_t bK   = ((lane >> 3) & 1) * 8;
    const uint32_t aBaseH = (uint32_t)__cvta_generic_to_shared(a_h) +
                            ((wm * 64 + aRow) * KPA + aK) * 2;
    const uint32_t bBase0 = (uint32_t)__cvta_generic_to_shared(bs) +
                            ((wn * 32 + bRow) * KPB + bK) * 2;

    const int NCHT = 32 * 4;
    loadB(0, 0); CP_COMMIT();
    loadB(1, 1); CP_COMMIT();
    for (int c = 0; c < NCHT; c++) {
        if (c + 2 < NCHT) loadB(c + 2, (c + 2) & 3);
        CP_COMMIT();
        CP_WAIT2();
        __syncthreads();
        const int kcc = c & 3;
        const uint32_t bSt = bBase0 + ((c & 3) * B_STGH) * 2;
#pragma unroll
        for (int ks = 0; ks < 2; ks++) {
            const int k0 = kcc * 32 + ks * 16;
            uint32_t af[4][4];
#pragma unroll
            for (int mt = 0; mt < 4; mt++)
                ldsm4(af[mt], aBaseH + (mt * 16 * KPA + k0) * 2);
            uint32_t bf[2][4];
#pragma unroll
            for (int pr = 0; pr < 2; pr++)
                ldsm4(bf[pr], bSt + (pr * 16 * KPB + ks * 16) * 2);
#pragma unroll
            for (int nt = 0; nt < 4; nt++) {
                uint32_t b0 = bf[nt >> 1][(nt & 1) * 2 + 0];
                uint32_t b1 = bf[nt >> 1][(nt & 1) * 2 + 1];
#pragma unroll
                for (int mt = 0; mt < 4; mt++)
                    mma16816(acc[mt][nt], af[mt][0], af[mt][1], af[mt][2], af[mt][3], b0, b1);
            }
        }
        if (kcc == 3) {
            const int ct = c >> 2;
#pragma unroll
            for (int mt = 0; mt < 4; mt++) {
#pragma unroll
                for (int nt = 0; nt < 4; nt++) {
                    const int col0 = ct * 128 + wn * 32 + nt * 8 + tq * 2;
#pragma unroll
                    for (int h = 0; h < 2; h++) {
#pragma unroll
                        for (int cc = 0; cc < 2; cc++) {
                            const int kg = col0 + cc;
                            float s1 = __fadd_rn(rnr[mt][h], cn_s[kg]);
                            float d  = __fadd_rn(s1, -2.0f * acc[mt][nt][2 * h + cc]);
                            if (d < bv[mt][h] || (d == bv[mt][h] && kg < bi[mt][h])) {
                                sv[mt][h] = bv[mt][h]; bv[mt][h] = d; bi[mt][h] = kg;
                            } else if (d < sv[mt][h]) {
                                sv[mt][h] = d;
                            }
                        }
                    }
                    acc[mt][nt][0] = 0.0f; acc[mt][nt][1] = 0.0f;
                    acc[mt][nt][2] = 0.0f; acc[mt][nt][3] = 0.0f;
                }
            }
        }
    }

#pragma unroll
    for (int mt = 0; mt < 4; mt++) {
#pragma unroll
        for (int h = 0; h < 2; h++) {
            float b = bv[mt][h], s = sv[mt][h];
            int   i = bi[mt][h];
#pragma unroll
            for (int m = 1; m <= 2; m <<= 1) {
                float b2 = __shfl_xor_sync(0xffffffffu, b, m);
                float s2 = __shfl_xor_sync(0xffffffffu, s, m);
                int   i2 = __shfl_xor_sync(0xffffffffu, i, m);
                if (b2 < b || (b2 == b && i2 < i)) { s = fminf(b, s2); b = b2; i = i2; }
                else s = fminf(s, b2);
            }
            if (tq == 0) {
                const int rl = wm * 64 + mt * 16 + gq + 8 * h;
                RV[rl * 4 + wn] = b; RS[rl * 4 + wn] = s; RI[rl * 4 + wn] = i;
            }
        }
    }
    __syncthreads();
    if (tid < 128) {
        float b = RV[tid * 4], s = RS[tid * 4];
        int   i = RI[tid * 4];
#pragma unroll
        for (int w = 1; w < 4; w++) {
            float b2 = RV[tid * 4 + w], s2 = RS[tid * 4 + w];
            int   i2 = RI[tid * 4 + w];
            if (b2 < b || (b2 == b && i2 < i)) { s = fminf(b, s2); b = b2; i = i2; }
            else s = fminf(s, b2);
        }
        g_idx[rbase + tid] = i;
        float thr = 72.0f * sqrtf(g_rn[rbase + tid]) * g_cnmax + 0.01f;
        if (s - b < thr) {
            int p = atomicAdd(&g_flagcnt, 1);
            g_flagrows[p] = rbase + tid;
        }
    }
}

// ---------------- Level-2 HMMA argmin — 3-pass, code-partitioned ----------------
static constexpr int ARG_SMEM2 =
    (256 * KPA + 4 * B_STGH) * 2 + (cK + 512 * 3) * 4 + 512;   // ~133.6KB

__global__ void __launch_bounds__(256)
argmin_l2() {
    extern __shared__ __align__(16) __half dsm[];
    __half* a_h = dsm;
    __half* a_l = dsm + 128 * KPA;
    __half* bs  = dsm + 256 * KPA;
    float*  cn_s = reinterpret_cast<float*>(dsm + 256 * KPA + 4 * B_STGH);
    float*  RV = cn_s + cK;
    float*  RS = RV + 512;
    int*    RI = reinterpret_cast<int*>(RS + 512);
    int*    rid_s = RI + 512;

    const int nf = g_flagcnt;
    const int ntiles = (nf + 127) >> 7;
    if ((int)blockIdx.x >= ntiles) return;

    const int tid = threadIdx.x;
    const int lane = tid & 31, warp = tid >> 5;
    const int wm = warp >> 2, wn = warp & 3;
    const int gq = lane >> 2, tq = lane & 3;
    const int base = blockIdx.x * 128;
    const int part = blockIdx.y;
    const int ct0 = part * L2_TILES_PER_PART;

    if (tid < 128) {
        int f = base + tid;
        rid_s[tid] = g_flagrows[(f < nf) ? f : (nf - 1)];
    }
    __syncthreads();

#pragma unroll
    for (int j = 0; j < 8; j++) {
        int i = tid + 256 * j;
        int row = i >> 4, seg = i & 15;
        int ridx = rid_s[row];
        *reinterpret_cast<uint4*>(a_h + row * KPA + seg * 8) =
            *reinterpret_cast<const uint4*>(g_latH + (size_t)ridx * cD + seg * 8);
        *reinterpret_cast<uint4*>(a_l + row * KPA + seg * 8) =
            *reinterpret_cast<const uint4*>(g_latL + (size_t)ridx * cD + seg * 8);
    }
    for (int i = tid; i < cK / 4; i += 256) {
        float4 v = reinterpret_cast<const float4*>(g_cn)[i];
        v.x *= 65536.0f; v.y *= 65536.0f; v.z *= 65536.0f; v.w *= 65536.0f;
        reinterpret_cast<float4*>(cn_s)[i] = v;
    }

    float rnr[4][2];
#pragma unroll
    for (int mt = 0; mt < 4; mt++)
#pragma unroll
        for (int h = 0; h < 2; h++)
            rnr[mt][h] = g_rn[rid_s[wm * 64 + mt * 16 + gq + 8 * h]] * 65536.0f;

    float bv[4][2], sv[4][2];
    int   bi[4][2];
#pragma unroll
    for (int mt = 0; mt < 4; mt++)
#pragma unroll
        for (int h = 0; h < 2; h++) { bv[mt][h] = INFINITY; sv[mt][h] = INFINITY; bi[mt][h] = 0; }

    float acc[4][4][4];
#pragma unroll
    for (int a = 0; a < 4; a++)
#pragma unroll
        for (int b = 0; b < 4; b++)
#pragma unroll
            for (int q = 0; q < 4; q++) acc[a][b][q] = 0.0f;

    auto loadB = [&](int c, int st) {
        const int ct = ct0 + c / 12, sub = c % 12;
        const __half* src = ((sub >> 2) == 0) ? g_cbL : g_cbH;
        const int kc = sub & 3;
#pragma unroll
        for (int j = 0; j < 2; j++) {
            int i = tid + 256 * j;
            int row = i >> 2, seg = i & 3;
            cp_async16(bs + st * B_STGH + row * KPB + seg * 8,
                       src + (size_t)(ct * 128 + row) * cD + kc * 32 + seg * 8);
        }
    };

    const uint32_t aRow = (lane & 7) + ((lane >> 3) & 1) * 8;
    const uint32_t aK   = (lane >> 4) * 8;
    const uint32_t bRow = ((lane >> 4) & 1) * 8 + (lane & 7);
    const uint32_t bK   = ((lane >> 3) & 1) * 8;
    const uint32_t aBaseH = (uint32_t)__cvta_generic_to_shared(a_h) +
                            ((wm * 64 + aRow) * KPA + aK) * 2;
    const uint32_t aBaseL = (uint32_t)__cvta_generic_to_shared(a_l) +
                            ((wm * 64 + aRow) * KPA + aK) * 2;
    const uint32_t bBase0 = (uint32_t)__cvta_generic_to_shared(bs) +
                            ((wn * 32 + bRow) * KPB + bK) * 2;

    const int NCHT = L2_TILES_PER_PART * 12;   // 96
    loadB(0, 0); CP_COMMIT();
    loadB(1, 1); CP_COMMIT();
    for (int c = 0; c < NCHT; c++) {
        if (c + 2 < NCHT) loadB(c + 2, (c + 2) & 3);
        CP_COMMIT();
        CP_WAIT2();
        __syncthreads();
        const int sub = c % 12;
        if (sub == 8) {
#pragma unroll
            for (int a = 0; a < 4; a++)
#pragma unroll
                for (int b = 0; b < 4; b++)
#pragma unroll
                    for (int q = 0; q < 4; q++) acc[a][b][q] *= INV_LO;
        }
        const int kcc = sub & 3;
        const uint32_t aBase = ((sub >> 2) == 1) ? aBaseL : aBaseH;
        const uint32_t bSt = bBase0 + ((c & 3) * B_STGH) * 2;
#pragma unroll
        for (int ks = 0; ks < 2; ks++) {
            const int k0 = kcc * 32 + ks * 16;
            uint32_t af[4][4];
#pragma unroll
            for (int mt = 0; mt < 4; mt++)
                ldsm4(af[mt], aBase + (mt * 16 * KPA + k0) * 2);
            uint32_t bf[2][4];
#pragma unroll
            for (int pr = 0; pr < 2; pr++)
                ldsm4(bf[pr], bSt + (pr * 16 * KPB + ks * 16) * 2);
#pragma unroll
            for (int nt = 0; nt < 4; nt++) {
                uint32_t b0 = bf[nt >> 1][(nt & 1) * 2 + 0];
                uint32_t b1 = bf[nt >> 1][(nt & 1) * 2 + 1];
#pragma unroll
                for (int mt = 0; mt < 4; mt++)
                    mma16816(acc[mt][nt], af[mt][0], af[mt][1], af[mt][2], af[mt][3], b0, b1);
            }
        }
        if (sub == 11) {
            const int ct = ct0 + c / 12;
#pragma unroll
            for (int mt = 0; mt < 4; mt++) {
#pragma unroll
                for (int nt = 0; nt < 4; nt++) {
                    const int col0 = ct * 128 + wn * 32 + nt * 8 + tq * 2;
#pragma unroll
                    for (int h = 0; h < 2; h++) {
#pragma unroll
                        for (int cc = 0; cc < 2; cc++) {
                            const int kg = col0 + cc;
                            float s1 = __fadd_rn(rnr[mt][h], cn_s[kg]);
                            float d  = __fadd_rn(s1, -2.0f * acc[mt][nt][2 * h + cc]);
                            if (d < bv[mt][h] || (d == bv[mt][h] && kg < bi[mt][h])) {
                                sv[mt][h] = bv[mt][h]; bv[mt][h] = d; bi[mt][h] = kg;
                            } else if (d < sv[mt][h]) {
                                sv[mt][h] = d;
                            }
                        }
                    }
                    acc[mt][nt][0] = 0.0f; acc[mt][nt][1] = 0.0f;
                    acc[mt][nt][2] = 0.0f; acc[mt][nt][3] = 0.0f;
                }
            }
        }
    }

#pragma unroll
    for (int mt = 0; mt < 4; mt++) {
#pragma unroll
        for (int h = 0; h < 2; h++) {
            float b = bv[mt][h], s = sv[mt][h];
            int   i = bi[mt][h];
#pragma unroll
            for (int m = 1; m <= 2; m <<= 1) {
                float b2 = __shfl_xor_sync(0xffffffffu, b, m);
                float s2 = __shfl_xor_sync(0xffffffffu, s, m);
                int   i2 = __shfl_xor_sync(0xffffffffu, i, m);
                if (b2 < b || (b2 == b && i2 < i)) { s = fminf(b, s2); b = b2; i = i2; }
                else s = fminf(s, b2);
            }
            if (tq == 0) {
                const int rl = wm * 64 + mt * 16 + gq + 8 * h;
                RV[rl * 4 + wn] = b; RS[rl * 4 + wn] = s; RI[rl * 4 + wn] = i;
            }
        }
    }
    __syncthreads();
    if (tid < 128 && base + tid < nf) {
        float b = RV[tid * 4], s = RS[tid * 4];
        int   i = RI[tid * 4];
#pragma unroll
        for (int w = 1; w < 4; w++) {
            float b2 = RV[tid * 4 + w], s2 = RS[tid * 4 + w];
            int   i2 = RI[tid * 4 + w];
            if (b2 < b || (b2 == b && i2 < i)) { s = fminf(b, s2); b = b2; i = i2; }
            else s = fminf(s, b2);
        }
        const int f = base + tid;
        g_l2v[f * L2_PARTS + part] = b;
        g_l2s[f * L2_PARTS + part] = s;
        g_l2i[f * L2_PARTS + part] = i;
    }
}

__global__ void l2_combine() {
    int f = blockIdx.x * 256 + threadIdx.x;
    const int nf = g_flagcnt;
    if (f >= nf) return;
    float b = g_l2v[f * L2_PARTS], s = g_l2s[f * L2_PARTS];
    int   i = g_l2i[f * L2_PARTS];
#pragma unroll
    for (int w = 1; w < L2_PARTS; w++) {
        float b2 = g_l2v[f * L2_PARTS + w], s2 = g_l2s[f * L2_PARTS + w];
        int   i2 = g_l2i[f * L2_PARTS + w];
        if (b2 < b || (b2 == b && i2 < i)) { s = fminf(b, s2); b = b2; i = i2; }
        else s = fminf(s, b2);
    }
    const int row = g_flagrows[f];
    g_idx[row] = i;
    if (s - b < EPS_SCALED) {
        int p = atomicAdd(&g_flagcnt2, 1);
        g_flagrows2[p] = row;
    }
}

// ---------------- Level-3 exact fp32 recheck ----------------
__global__ void __launch_bounds__(256)
recheck_k(const float* __restrict__ cb) {
    __shared__ float lrow[32][cD + 4];
    __shared__ float crow[8][cD + 4];
    __shared__ int   rowid[32];
    __shared__ float rnv[32];
    const int tid = threadIdx.x;
    const int nf = g_flagcnt2;
    const int ntiles = (nf + 31) >> 5;
    const int r = tid >> 3;
    const int cl = tid & 7;

    for (int tile = blockIdx.x; tile < ntiles; tile += gridDim.x) {
        __syncthreads();
        if (tid < 32) {
            int f = tile * 32 + tid;
            int row = (f < nf) ? g_flagrows2[f] : -1;
            rowid[tid] = row;
            rnv[tid] = (row >= 0) ? g_rn[row] : 0.0f;
        }
        __syncthreads();
        for (int i = tid; i < 32 * 32; i += 256) {
            int rr = i >> 5, seg = i & 31;
            int row = rowid[rr];
            float4 v = (row >= 0)
                ? reinterpret_cast<const float4*>(g_lat + (size_t)row * cD)[seg]
                : make_float4(0.f, 0.f, 0.f, 0.f);
            *reinterpret_cast<float4*>(&lrow[rr][seg * 4]) = v;
        }
        __syncthreads();

        float bvv = INFINITY; int bii = 0;
        const float rn = rnv[r];
        for (int k0 = 0; k0 < cK; k0 += 8) {
            {
                int cr = tid >> 5, seg = tid & 31;
                *reinterpret_cast<float4*>(&crow[cr][seg * 4]) =
                    reinterpret_cast<const float4*>(cb + (size_t)(k0 + cr) * cD)[seg];
            }
            __syncthreads();
            float dot = 0.0f;
#pragma unroll
            for (int d4 = 0; d4 < 32; d4++) {
                float4 a = *reinterpret_cast<const float4*>(&lrow[r][d4 * 4]);
                float4 b = *reinterpret_cast<const float4*>(&crow[cl][d4 * 4]);
                dot = fmaf(a.x, b.x, dot); dot = fmaf(a.y, b.y, dot);
                dot = fmaf(a.z, b.z, dot); dot = fmaf(a.w, b.w, dot);
            }
            const int k = k0 + cl;
            float s1 = __fadd_rn(rn, g_cn[k]);
            float dd = __fadd_rn(s1, -2.0f * dot);
            if (dd < bvv) { bvv = dd; bii = k; }
            __syncthreads();
        }
#pragma unroll
        for (int m = 1; m <= 4; m <<= 1) {
            float b2 = __shfl_xor_sync(0xffffffffu, bvv, m);
            int   i2 = __shfl_xor_sync(0xffffffffu, bii, m);
            if (b2 < bvv || (b2 == bvv && i2 < bii)) { bvv = b2; bii = i2; }
        }
        if (cl == 0 && rowid[r] >= 0) g_idx[rowid[r]] = bii;
    }
}

// gather: 64 rows/block, one atomic per block
__global__ void __launch_bounds__(256)
gather_vq(const float* __restrict__ cb, float* __restrict__ outIdxF) {
    __shared__ float wsum[8];
    const int tid = threadIdx.x;
    const int warp = tid >> 5, lane = tid & 31;
    float s = 0.0f;
#pragma unroll
    for (int it = 0; it < 8; it++) {
        const int row = blockIdx.x * 64 + warp * 8 + it;
        const int id = g_idx[row];
        float4 c = reinterpret_cast<const float4*>(cb)[(size_t)id * 32 + lane];
        float4 l = reinterpret_cast<const float4*>(g_lat)[(size_t)row * 32 + lane];
        if (lane < 16) {
            reinterpret_cast<uint4*>(g_qH + (size_t)row * cD)[lane] =
                reinterpret_cast<const uint4*>(g_cbH + (size_t)id * cD)[lane];
        } else {
            reinterpret_cast<uint4*>(g_qL + (size_t)row * cD)[lane - 16] =
                reinterpret_cast<const uint4*>(g_cbL + (size_t)id * cD)[lane - 16];
        }
        float dx = c.x - l.x, dy = c.y - l.y, dz = c.z - l.z, dw = c.w - l.w;
        s += dx * dx + dy * dy + dz * dz + dw * dw;
        if (lane == 0 && outIdxF) outIdxF[row] = (float)id;
    }
#pragma unroll
    for (int off = 16; off > 0; off >>= 1) s += __shfl_down_sync(0xffffffffu, s, off);
    if (lane == 0) wsum[warp] = s;
    __syncthreads();
    if (tid == 0) {
        float t = 0.0f;
#pragma unroll
        for (int w = 0; w < 8; w++) t += wsum[w];
        atomicAdd(&g_vq_sum, t);
    }
}

__global__ void finalize_k(float* __restrict__ out, int out_size) {
    if (out_size >= FULL_OUT) {
        float m = g_vq_sum / (float)(cB * cN * cD);
        float vq = 1.25f * m;
        float rl = g_recon_sum / (float)RECON_ELEMS;
        out[SCALAR_OFF + 0] = vq;
        out[SCALAR_OFF + 1] = rl;
        out[SCALAR_OFF + 2] = rl + vq;
    }
}

// ---------------- launch ----------------
extern "C" void kernel_launch(void* const* d_in, const int* in_sizes, int n_in,
                              void* d_out, int out_size) {
    const float* actions = (const float*)d_in[0];
    const float* e_w1 = (const float*)d_in[1];
    const float* e_b1 = (const float*)d_in[2];
    const float* e_w2 = (const float*)d_in[3];
    const float* e_b2 = (const float*)d_in[4];
    const float* e_w3 = (const float*)d_in[5];
    const float* e_b3 = (const float*)d_in[6];
    const float* cb   = (const float*)d_in[7];
    const float* d_w1 = (const float*)d_in[8];
    const float* d_b1 = (const float*)d_in[9];
    const float* d_w2 = (const float*)d_in[10];
    const float* d_b2 = (const float*)d_in[11];
    const float* d_w3 = (const float*)d_in[12];
    const float* d_b3 = (const float*)d_in[13];
    float* out = (float*)d_out;

    float *p_h1, *p_h2, *p_lat;
    cudaGetSymbolAddress((void**)&p_h1,  g_h1);
    cudaGetSymbolAddress((void**)&p_h2,  g_h2);
    cudaGetSymbolAddress((void**)&p_lat, g_lat);
    __half *latH, *latL, *qH, *qL, *g1H, *g1L, *g2H, *g2L, *cbH, *cbL;
    __half *v1H, *v1L, *v2H, *v2L, *v3H, *v3L;
    cudaGetSymbolAddress((void**)&latH, g_latH); cudaGetSymbolAddress((void**)&latL, g_latL);
    cudaGetSymbolAddress((void**)&qH, g_qH);     cudaGetSymbolAddress((void**)&qL, g_qL);
    cudaGetSymbolAddress((void**)&g1H, g_g1H);   cudaGetSymbolAddress((void**)&g1L, g_g1L);
    cudaGetSymbolAddress((void**)&g2H, g_g2H);   cudaGetSymbolAddress((void**)&g2L, g_g2L);
    cudaGetSymbolAddress((void**)&cbH, g_cbH);   cudaGetSymbolAddress((void**)&cbL, g_cbL);
    cudaGetSymbolAddress((void**)&v1H, g_v1H);   cudaGetSymbolAddress((void**)&v1L, g_v1L);
    cudaGetSymbolAddress((void**)&v2H, g_v2H);   cudaGetSymbolAddress((void**)&v2L, g_v2L);
    cudaGetSymbolAddress((void**)&v3H, g_v3H);   cudaGetSymbolAddress((void**)&v3L, g_v3L);

    static cudaStream_t s2 = nullptr;
    static cudaEvent_t evFork = nullptr, evA = nullptr, evC = nullptr;
    static bool attr_done = false;
    if (!attr_done) {
        cudaFuncSetAttribute(argmin_l1, cudaFuncAttributeMaxDynamicSharedMemorySize, ARG_SMEM1);
        cudaFuncSetAttribute(argmin_l2, cudaFuncAttributeMaxDynamicSharedMemorySize, ARG_SMEM2);
        cudaFuncSetAttribute((const void*)mma_gemm<1, 1>, cudaFuncAttributeMaxDynamicSharedMemorySize, DEC_SMEM);
        cudaFuncSetAttribute((const void*)mma_gemm<2, 1>, cudaFuncAttributeMaxDynamicSharedMemorySize, DEC_SMEM);
        cudaStreamCreateWithFlags(&s2, cudaStreamNonBlocking);
        cudaEventCreateWithFlags(&evFork, cudaEventDisableTiming);
        cudaEventCreateWithFlags(&evA, cudaEventDisableTiming);
        cudaEventCreateWithFlags(&evC, cudaEventDisableTiming);
        attr_done = true;
    }

    const bool has_idx = out_size >= (IDX_OFF + cROWS);
    dim3 wt(32, 8);

    // fork: prep chain on s2 (independent of encoder)
    cudaEventRecord(evFork, 0);
    cudaStreamWaitEvent(s2, evFork, 0);
    cn_kernel<<<cK / 8, 256, 0, s2>>>(cb);
    cnmax_kernel<<<1, 256, 0, s2>>>();
    split_act<<<(cK * cD / 4 + 255) / 256, 256, 0, s2>>>(cb, cbH, cbL, cK * cD / 4);
    wsplit<<<dim3(cHID / 32, cLAT / 32), wt, 0, s2>>>(d_w1, v1H, v1L, cLAT, cHID);
    wsplit<<<dim3(cHID / 32, cHID / 32), wt, 0, s2>>>(d_w2, v2H, v2L, cHID, cHID);
    wsplit<<<dim3(cFLAT / 32 + 1, cHID / 32), wt, 0, s2>>>(d_w3, v3H, v3L, cHID, cFLAT);

    // main: encoder (fp32, bit-identical arithmetic); enc3 split into halves
    init_accum<<<1, 1>>>();
    sgemm_k<1, false><<<dim3(cHID / BN, cB / BM), 256>>>(actions, e_w1, e_b1, p_h1, cB, cHID, cFLAT, nullptr, nullptr, 0);
    sgemm_k<1, false><<<dim3(cHID / BN, cB / BM), 256>>>(p_h1, e_w2, e_b2, p_h2, cB, cHID, cHID, nullptr, nullptr, 0);
    sgemm_k<0, true><<<dim3(cLAT / BN, cB / BM / 2), 256>>>(p_h2, e_w3, e_b3, p_lat, cB, cLAT, cHID, latH, latL, 0);
    cudaEventRecord(evA, 0);

    // s2: first-half argmin L1 overlapped with second-half enc3
    cudaStreamWaitEvent(s2, evA, 0);
    rn_kernel<<<cROWS / 16, 256, 0, s2>>>(0);
    argmin_l1<<<cROWS / 256, 256, ARG_SMEM1, s2>>>(0);
    cudaEventRecord(evC, s2);

    // main: second half enc3 + its argmin
    sgemm_k<0, true><<<dim3(cLAT / BN, cB / BM / 2), 256>>>(p_h2, e_w3, e_b3, p_lat, cB, cLAT, cHID, latH, latL, cB / BM / 2);
    rn_kernel<<<cROWS / 16, 256>>>(cROWS / 2);
    argmin_l1<<<cROWS / 256, 256, ARG_SMEM1>>>(cROWS / 256);
    cudaStreamWaitEvent(0, evC, 0);

    // quantization — hierarchical argmin tail
    argmin_l2<<<dim3(cROWS / 128, L2_PARTS), 256, ARG_SMEM2>>>();
    l2_combine<<<cROWS / 256, 256>>>();
    recheck_k<<<148, 256>>>(cb);
    gather_vq<<<cROWS / 64, 256>>>(cb, has_idx ? (out + IDX_OFF) : nullptr);

    // decoder — d1/d2/d3 all 1-pass (hh) split-fp16 HMMA
    mma_gemm<1, 1><<<dim3(cHID / 128, cB / 128), 256, DEC_SMEM>>>(qH, qL, v1H, v1L, d_b1, nullptr, g1H, g1L, cB, cHID, cLAT, nullptr);
    mma_gemm<1, 1><<<dim3(cHID / 128, cB / 128), 256, DEC_SMEM>>>(g1H, g1L, v2H, v2L, d_b2, nullptr, g2H, g2L, cB, cHID, cHID, nullptr);
    mma_gemm<2, 1><<<dim3(1, cB / 128), 256, DEC_SMEM>>>(g2H, g2L, v3H, v3L, d_b3, out, nullptr, nullptr, cB, cFLAT, cHID, actions);

    finalize_k<<<1, 1>>>(out, out_size);
}